// round 7
// baseline (speedup 1.0000x reference)
#include <cuda_runtime.h>
#include <cuda_bf16.h>
#include <cstdint>
#include <math.h>

#define TILE_E   64
#define NTHREADS 256
#define HDIM     128
#define STRIDE1B 144   // bytes/row, GEMM1 tiles (36 words -> conflict-free ldsm)
#define STRIDE2B 272   // bytes/row, GEMM2 tiles (68 words -> conflict-free ldsm)

// ---------------- global scratch: transposed + hi/lo split weights ----------------
__device__ __nv_bfloat16 g_W1T_h[128 * 512];   // [n][k] from W1[k][n]
__device__ __nv_bfloat16 g_W1T_l[128 * 512];
__device__ __nv_bfloat16 g_W2T_h[64 * 128];    // [n][k] from W2[k][n]
__device__ __nv_bfloat16 g_W2T_l[64 * 128];

__global__ void prep_kernel(const float* __restrict__ W1, const float* __restrict__ W2) {
    int i = blockIdx.x * blockDim.x + threadIdx.x;
    if (i < 128 * 512) {
        int n = i >> 9, k = i & 511;
        float x = W1[k * 128 + n];
        __nv_bfloat16 h = __float2bfloat16(x);
        g_W1T_h[i] = h;
        g_W1T_l[i] = __float2bfloat16(x - __bfloat162float(h));
    }
    if (i < 64 * 128) {
        int n = i >> 7, k = i & 127;
        float x = W2[k * 64 + n];
        __nv_bfloat16 h = __float2bfloat16(x);
        g_W2T_h[i] = h;
        g_W2T_l[i] = __float2bfloat16(x - __bfloat162float(h));
    }
}

// ---------------- helpers ----------------
__device__ __forceinline__ uint32_t smem_u32(const void* p) {
    uint32_t a;
    asm("{ .reg .u64 t; cvta.to.shared.u64 t, %1; cvt.u32.u64 %0, t; }" : "=r"(a) : "l"(p));
    return a;
}
#define STS32(addr, v) \
    asm volatile("st.shared.b32 [%0], %1;" :: "r"(addr), "r"(v) : "memory")
#define CP16(saddr, gaddr) \
    asm volatile("cp.async.cg.shared.global [%0], [%1], 16;" \
        :: "r"(saddr), "l"(gaddr) : "memory")
#define CP_COMMIT() asm volatile("cp.async.commit_group;" ::: "memory")
#define CP_WAIT0()  asm volatile("cp.async.wait_group 0;" ::: "memory")
#define LDSM4(r, a) \
    asm volatile("ldmatrix.sync.aligned.m8n8.x4.shared.b16 {%0,%1,%2,%3}, [%4];" \
        : "=r"((r)[0]), "=r"((r)[1]), "=r"((r)[2]), "=r"((r)[3]) : "r"(a))
#define MMA16816(c, a, b0v, b1v) \
    asm volatile("mma.sync.aligned.m16n8k16.row.col.f32.bf16.bf16.f32 " \
        "{%0,%1,%2,%3}, {%4,%5,%6,%7}, {%8,%9}, {%0,%1,%2,%3};" \
        : "+f"((c)[0]), "+f"((c)[1]), "+f"((c)[2]), "+f"((c)[3]) \
        : "r"((a)[0]), "r"((a)[1]), "r"((a)[2]), "r"((a)[3]), "r"(b0v), "r"(b1v))

// pack 2 floats to bf16x2 (hi) and residual bf16x2 (lo); rn rounding, same
// numerics as __float2bfloat16 but fewer instructions.
__device__ __forceinline__ uint32_t split2(float x0, float x1, uint32_t& lo2) {
    uint32_t hi2;
    asm("cvt.rn.bf16x2.f32 %0, %1, %2;" : "=r"(hi2) : "f"(x1), "f"(x0));
    float h0 = __uint_as_float(hi2 << 16);
    float h1 = __uint_as_float(hi2 & 0xffff0000u);
    float l0 = x0 - h0, l1 = x1 - h1;
    asm("cvt.rn.bf16x2.f32 %0, %1, %2;" : "=r"(lo2) : "f"(l1), "f"(l0));
    return hi2;
}

// GEMM1 double-buffer layout (per half): A hi | A lo | B hi | B lo
//   A: 64 x 144B, B: 128 x 144B
#define B1_AH 0
#define B1_AL 9216
#define B1_BH 18432
#define B1_BL 36864
#define BUF1_BYTES 55296
// GEMM2 overlays (after GEMM1): A2 in buf0, B2 in buf1, s_part in buf0 spare
#define G2_AH 0               // 64 x 272B = 17408
#define G2_AL 17408
#define G2_PART 34816         // float[64][4] = 1024B (buf0 spare)
#define G2_BH 55296           // 64 x 272B
#define G2_BL 72704
#define SMEM_DYN (2 * BUF1_BYTES)   // 110592

__global__ __launch_bounds__(NTHREADS, 2)
void link_mma_kernel(const float* __restrict__ z,
                     const void* __restrict__ ei_raw,
                     const float* __restrict__ b1g,
                     const float* __restrict__ b2g,
                     const float* __restrict__ w3g,
                     const float* __restrict__ b3g,
                     float* __restrict__ out,
                     int E, int nNodes)
{
    extern __shared__ char dynraw[];
    __shared__ int s_src[TILE_E], s_dst[TILE_E];
    __shared__ int s_is64;

    const int tid = threadIdx.x;
    const int wid = tid >> 5;
    const int lid = tid & 31;
    const int e0  = blockIdx.x * TILE_E;
    const uint32_t sb = smem_u32(dynraw);

    // ---- setup ----
    if (tid == 0) {
        const long long* e64 = (const long long*)ei_raw;
        int ok = 1;
        #pragma unroll
        for (int i = 0; i < 8; ++i) {
            long long v = e64[i];
            if (v < 0 || v >= (long long)nNodes) { ok = 0; break; }
        }
        s_is64 = ok;
    }
    __syncthreads();
    if (tid < 128) {
        const int is64 = s_is64;
        int t = tid & (TILE_E - 1);
        int e = e0 + t; if (e >= E) e = 0;
        int v;
        if (tid < TILE_E) {
            v = is64 ? (int)((const long long*)ei_raw)[e] : ((const int*)ei_raw)[e];
            s_src[t] = min(max(v, 0), nNodes - 1);
        } else {
            v = is64 ? (int)((const long long*)ei_raw)[(size_t)E + e]
                     : ((const int*)ei_raw)[(size_t)E + e];
            s_dst[t] = min(max(v, 0), nNodes - 1);
        }
    }
    __syncthreads();

    const int wm = wid >> 2;       // 0..1 : 32-row band
    const int wn = wid & 3;        // 0..3 : 32-col band (GEMM1) / 16-col (GEMM2)
    const uint32_t lrow = (uint32_t)(lid & 15);
    const uint32_t lcol = (uint32_t)(lid >> 4) * 8;

    // ---- pipeline stage helpers ----
    float2 vs[8], vd[8];
    auto stageA = [&](int c) {
        const int half = (c & 1) * 64;
        #pragma unroll
        for (int i = 0; i < 8; ++i) {
            int m = (wid << 3) + i;      // 8 warps x 8 = 64 edges
            vs[i] = *(const float2*)(z + (size_t)s_src[m] * HDIM + half + 2 * lid);
            vd[i] = *(const float2*)(z + (size_t)s_dst[m] * HDIM + half + 2 * lid);
        }
    };
    auto stsA = [&](int c, uint32_t buf) {
        const int seg = c >> 1;
        const uint32_t ah = buf + B1_AH, al = buf + B1_AL;
        #pragma unroll
        for (int i = 0; i < 8; ++i) {
            int m = (wid << 3) + i;
            float2 v;
            if (seg == 0)      v = vs[i];
            else if (seg == 1) v = vd[i];
            else if (seg == 2) { v.x = vs[i].x * vd[i].x;        v.y = vs[i].y * vd[i].y; }
            else               { v.x = fabsf(vs[i].x - vd[i].x); v.y = fabsf(vs[i].y - vd[i].y); }
            uint32_t lo2, hi2 = split2(v.x, v.y, lo2);
            uint32_t off = (uint32_t)m * STRIDE1B + (uint32_t)lid * 4;
            STS32(ah + off, hi2);
            STS32(al + off, lo2);
        }
    };
    auto cpB1 = [&](int c, uint32_t buf) {
        const char* srcH = (const char*)g_W1T_h;
        const char* srcL = (const char*)g_W1T_l;
        #pragma unroll
        for (int it = 0; it < 4; ++it) {
            int idx = tid + it * NTHREADS;     // 0..1023
            int n = idx >> 3, q = idx & 7;
            uint32_t goff = (uint32_t)n * 1024u + (uint32_t)c * 128u + (uint32_t)q * 16u;
            uint32_t soff = (uint32_t)n * STRIDE1B + (uint32_t)q * 16u;
            CP16(buf + B1_BH + soff, srcH + goff);
            CP16(buf + B1_BL + soff, srcL + goff);
        }
    };

    // ---- GEMM1: acc[2][4][4], 8 k-chunks of 64, register-staged pipeline ----
    float acc[2][4][4];
    #pragma unroll
    for (int a = 0; a < 2; ++a)
        #pragma unroll
        for (int b = 0; b < 4; ++b)
            #pragma unroll
            for (int d = 0; d < 4; ++d) acc[a][b][d] = 0.f;

    stageA(0);
    stsA(0, sb);
    cpB1(0, sb);
    CP_COMMIT();
    CP_WAIT0();
    __syncthreads();

    for (int c = 0; c < 8; ++c) {
        const uint32_t buf  = sb + (uint32_t)(c & 1) * BUF1_BYTES;
        const uint32_t nbuf = sb + (uint32_t)((c + 1) & 1) * BUF1_BYTES;
        if (c < 7) {
            cpB1(c + 1, nbuf);      // async, no registers
            CP_COMMIT();
            stageA(c + 1);          // gathers in flight during MMA below
        }
        // ---- MMA on chunk c (warp tile 32x32) ----
        {
            const uint32_t rowoff = (wm * 32u + lrow) * STRIDE1B + lcol * 2u;
            const uint32_t noff   = (wn * 32u + lrow) * STRIDE1B + lcol * 2u;
            const uint32_t aH = buf + B1_AH + rowoff;
            const uint32_t aL = buf + B1_AL + rowoff;
            const uint32_t bH = buf + B1_BH + noff;
            const uint32_t bL = buf + B1_BL + noff;
            #pragma unroll
            for (int ks = 0; ks < 4; ++ks) {
                const uint32_t ko = (uint32_t)ks * 32u;
                uint32_t ah[2][4], al[2][4], bh[2][4], bl[2][4];
                LDSM4(ah[0], aH + ko);
                LDSM4(ah[1], aH + ko + 16u * STRIDE1B);
                LDSM4(al[0], aL + ko);
                LDSM4(al[1], aL + ko + 16u * STRIDE1B);
                LDSM4(bh[0], bH + ko);
                LDSM4(bh[1], bH + ko + 16u * STRIDE1B);
                LDSM4(bl[0], bL + ko);
                LDSM4(bl[1], bL + ko + 16u * STRIDE1B);
                #pragma unroll
                for (int fm = 0; fm < 2; ++fm)
                    #pragma unroll
                    for (int fn = 0; fn < 4; ++fn) {
                        const int g = fn >> 1, sel = fn & 1;
                        MMA16816(acc[fm][fn], ah[fm], bh[g][sel], bh[g][sel + 2]);
                        MMA16816(acc[fm][fn], ah[fm], bl[g][sel], bl[g][sel + 2]);
                        MMA16816(acc[fm][fn], al[fm], bh[g][sel], bh[g][sel + 2]);
                    }
            }
        }
        if (c < 7) stsA(c + 1, nbuf);
        CP_WAIT0();
        __syncthreads();
    }

    // ---- epilogue 1: cp.async B2 into buf1; relu(+b1), split, A2 into buf0 ----
    {
        // B2 first (async, overlaps the scalar epilogue below)
        const char* srcH = (const char*)g_W2T_h;
        const char* srcL = (const char*)g_W2T_l;
        #pragma unroll
        for (int it = 0; it < 4; ++it) {
            int idx = tid + it * NTHREADS;     // 0..1023
            int n = idx >> 4, q = idx & 15;
            uint32_t goff = (uint32_t)n * 256u + (uint32_t)q * 16u;
            uint32_t soff = (uint32_t)n * STRIDE2B + (uint32_t)q * 16u;
            CP16(sb + G2_BH + soff, srcH + goff);
            CP16(sb + G2_BL + soff, srcL + goff);
        }
        CP_COMMIT();

        const uint32_t a2h = sb + G2_AH, a2l = sb + G2_AL;
        #pragma unroll
        for (int fm = 0; fm < 2; ++fm)
            #pragma unroll
            for (int fn = 0; fn < 4; ++fn) {
                const int col  = wn * 32 + fn * 8 + (lid & 3) * 2;
                const int row0 = wm * 32 + fm * 16 + (lid >> 2);
                const float bb0 = __ldg(&b1g[col]);
                const float bb1 = __ldg(&b1g[col + 1]);
                float x0 = fmaxf(acc[fm][fn][0] + bb0, 0.f);
                float x1 = fmaxf(acc[fm][fn][1] + bb1, 0.f);
                float x2 = fmaxf(acc[fm][fn][2] + bb0, 0.f);
                float x3 = fmaxf(acc[fm][fn][3] + bb1, 0.f);
                uint32_t lo2, hi2;
                uint32_t o0 = (uint32_t)row0 * STRIDE2B + (uint32_t)col * 2;
                hi2 = split2(x0, x1, lo2);
                STS32(a2h + o0, hi2); STS32(a2l + o0, lo2);
                uint32_t o1 = o0 + 8u * STRIDE2B;
                hi2 = split2(x2, x3, lo2);
                STS32(a2h + o1, hi2); STS32(a2l + o1, lo2);
            }
        CP_WAIT0();
    }
    __syncthreads();

    // ---- GEMM2: [64,128] x [64,128]^T -> acc2[2][2][4] (warp tile 32x16) ----
    float acc2[2][2][4];
    #pragma unroll
    for (int a = 0; a < 2; ++a)
        #pragma unroll
        for (int b = 0; b < 2; ++b)
            #pragma unroll
            for (int d = 0; d < 4; ++d) acc2[a][b][d] = 0.f;
    {
        const uint32_t rowoff = (wm * 32u + lrow) * STRIDE2B + lcol * 2u;
        const uint32_t noff   = (wn * 16u + lrow) * STRIDE2B + lcol * 2u;
        const uint32_t a2H = sb + G2_AH + rowoff;
        const uint32_t a2L = sb + G2_AL + rowoff;
        const uint32_t b2H = sb + G2_BH + noff;
        const uint32_t b2L = sb + G2_BL + noff;
        #pragma unroll
        for (int ks = 0; ks < 8; ++ks) {
            const uint32_t ko = (uint32_t)ks * 32u;
            uint32_t ah[2][4], al[2][4], bh[4], bl[4];
            LDSM4(ah[0], a2H + ko);
            LDSM4(ah[1], a2H + ko + 16u * STRIDE2B);
            LDSM4(al[0], a2L + ko);
            LDSM4(al[1], a2L + ko + 16u * STRIDE2B);
            LDSM4(bh, b2H + ko);
            LDSM4(bl, b2L + ko);
            #pragma unroll
            for (int fm = 0; fm < 2; ++fm)
                #pragma unroll
                for (int fn = 0; fn < 2; ++fn) {
                    MMA16816(acc2[fm][fn], ah[fm], bh[fn], bh[fn + 2]);
                    MMA16816(acc2[fm][fn], ah[fm], bl[fn], bl[fn + 2]);
                    MMA16816(acc2[fm][fn], al[fm], bh[fn], bh[fn + 2]);
                }
        }
    }

    // ---- epilogue 2: relu(+b2), dot w3, quad-reduce, cross-band add ----
    const uint32_t spart = sb + G2_PART;
    #pragma unroll
    for (int fm = 0; fm < 2; ++fm)
        #pragma unroll
        for (int rh = 0; rh < 2; ++rh) {
            float s = 0.f;
            #pragma unroll
            for (int fn = 0; fn < 2; ++fn) {
                const int col = wn * 16 + fn * 8 + (lid & 3) * 2;
                float h0 = fmaxf(acc2[fm][fn][rh * 2 + 0] + __ldg(&b2g[col]),     0.f);
                float h1 = fmaxf(acc2[fm][fn][rh * 2 + 1] + __ldg(&b2g[col + 1]), 0.f);
                s = fmaf(h0, __ldg(&w3g[col]), fmaf(h1, __ldg(&w3g[col + 1]), s));
            }
            s += __shfl_xor_sync(0xffffffffu, s, 1);
            s += __shfl_xor_sync(0xffffffffu, s, 2);
            if ((lid & 3) == 0) {
                int row = wm * 32 + fm * 16 + rh * 8 + (lid >> 2);
                STS32(spart + (uint32_t)(row * 4 + wn) * 4u, __float_as_uint(s));
            }
        }
    __syncthreads();
    if (tid < TILE_E) {
        const float* part = (const float*)(dynraw + G2_PART);
        int e = e0 + tid;
        if (e < E)
            out[e] = part[tid * 4 + 0] + part[tid * 4 + 1]
                   + part[tid * 4 + 2] + part[tid * 4 + 3] + __ldg(&b3g[0]);
    }
}

extern "C" void kernel_launch(void* const* d_in, const int* in_sizes, int n_in,
                              void* d_out, int out_size) {
    const float* z  = (const float*)d_in[0];
    const void*  ei = d_in[1];
    const float* W1 = (const float*)d_in[2];
    const float* b1 = (const float*)d_in[3];
    const float* W2 = (const float*)d_in[4];
    const float* b2 = (const float*)d_in[5];
    const float* W3 = (const float*)d_in[6];
    const float* b3 = (const float*)d_in[7];
    float* out = (float*)d_out;

    const int E      = out_size;
    const int nNodes = in_sizes[0] / HDIM;

    prep_kernel<<<256, 256>>>(W1, W2);

    cudaFuncSetAttribute(link_mma_kernel,
                         cudaFuncAttributeMaxDynamicSharedMemorySize, SMEM_DYN);
    const int grid = (E + TILE_E - 1) / TILE_E;
    link_mma_kernel<<<grid, NTHREADS, SMEM_DYN>>>(z, ei, b1, b2, W3, b3,
                                                  out, E, nNodes);
}

// round 8
// speedup vs baseline: 1.3723x; 1.3723x over previous
#include <cuda_runtime.h>
#include <cuda_bf16.h>
#include <cstdint>
#include <math.h>

#define TILE_E   128
#define NTHREADS 512
#define HDIM     128
#define STRIDE1B 144   // bytes/row, GEMM1 tiles (36 words -> conflict-free ldsm)
#define STRIDE2B 272   // bytes/row, GEMM2 tiles (68 words -> conflict-free ldsm)

// ---------------- global scratch: transposed + hi/lo split weights ----------------
// W1T is stored in CHUNK-REORDERED layout: new_k = c*64 + j where chunk c
// covers segment (c&3) in {src,dst,prod,diff} and half (c>>2) in {0,1}:
//   orig_k = (c&3)*128 + (c>>2)*64 + j
__device__ __nv_bfloat16 g_W1T_h[128 * 512];   // [n][new_k]
__device__ __nv_bfloat16 g_W1T_l[128 * 512];
__device__ __nv_bfloat16 g_W2T_h[64 * 128];    // [n][k] from W2[k][n]
__device__ __nv_bfloat16 g_W2T_l[64 * 128];

__global__ void prep_kernel(const float* __restrict__ W1, const float* __restrict__ W2) {
    int i = blockIdx.x * blockDim.x + threadIdx.x;
    if (i < 128 * 512) {
        int n = i >> 9, nk = i & 511;
        int c = nk >> 6, j = nk & 63;
        int orig_k = (c & 3) * 128 + (c >> 2) * 64 + j;
        float x = W1[orig_k * 128 + n];
        __nv_bfloat16 h = __float2bfloat16(x);
        g_W1T_h[i] = h;
        g_W1T_l[i] = __float2bfloat16(x - __bfloat162float(h));
    }
    if (i < 64 * 128) {
        int n = i >> 7, k = i & 127;
        float x = W2[k * 64 + n];
        __nv_bfloat16 h = __float2bfloat16(x);
        g_W2T_h[i] = h;
        g_W2T_l[i] = __float2bfloat16(x - __bfloat162float(h));
    }
}

// ---------------- helpers ----------------
__device__ __forceinline__ uint32_t smem_u32(const void* p) {
    uint32_t a;
    asm("{ .reg .u64 t; cvta.to.shared.u64 t, %1; cvt.u32.u64 %0, t; }" : "=r"(a) : "l"(p));
    return a;
}
#define STS32(addr, v) \
    asm volatile("st.shared.b32 [%0], %1;" :: "r"(addr), "r"(v) : "memory")
#define CP16(saddr, gaddr) \
    asm volatile("cp.async.cg.shared.global [%0], [%1], 16;" \
        :: "r"(saddr), "l"(gaddr) : "memory")
#define CP_COMMIT() asm volatile("cp.async.commit_group;" ::: "memory")
#define CP_WAIT0()  asm volatile("cp.async.wait_group 0;" ::: "memory")
#define LDSM4(r, a) \
    asm volatile("ldmatrix.sync.aligned.m8n8.x4.shared.b16 {%0,%1,%2,%3}, [%4];" \
        : "=r"((r)[0]), "=r"((r)[1]), "=r"((r)[2]), "=r"((r)[3]) : "r"(a))
#define MMA16816(c, a, b0v, b1v) \
    asm volatile("mma.sync.aligned.m16n8k16.row.col.f32.bf16.bf16.f32 " \
        "{%0,%1,%2,%3}, {%4,%5,%6,%7}, {%8,%9}, {%0,%1,%2,%3};" \
        : "+f"((c)[0]), "+f"((c)[1]), "+f"((c)[2]), "+f"((c)[3]) \
        : "r"((a)[0]), "r"((a)[1]), "r"((a)[2]), "r"((a)[3]), "r"(b0v), "r"(b1v))

__device__ __forceinline__ uint32_t split2(float x0, float x1, uint32_t& lo2) {
    uint32_t hi2;
    asm("cvt.rn.bf16x2.f32 %0, %1, %2;" : "=r"(hi2) : "f"(x1), "f"(x0));
    float h0 = __uint_as_float(hi2 << 16);
    float h1 = __uint_as_float(hi2 & 0xffff0000u);
    float l0 = x0 - h0, l1 = x1 - h1;
    asm("cvt.rn.bf16x2.f32 %0, %1, %2;" : "=r"(lo2) : "f"(l1), "f"(l0));
    return hi2;
}

// GEMM1 double-buffer layout (per half): A hi | A lo | B hi | B lo  (each 128x144B)
#define B1_AH 0
#define B1_AL 18432
#define B1_BH 36864
#define B1_BL 55296
#define BUF1_BYTES 73728
// GEMM2: A2 overlays buf0 after GEMM1; B2 dedicated (prefetched at start)
#define G2_AH 0               // 128 x 272B = 34816
#define G2_AL 34816
#define G2_BH 147456          // 64 x 272B = 17408
#define G2_BL 164864
#define SMEM_DYN 182272

__global__ __launch_bounds__(NTHREADS, 1)
void link_mma_kernel(const float* __restrict__ z,
                     const void* __restrict__ ei_raw,
                     const float* __restrict__ b1g,
                     const float* __restrict__ b2g,
                     const float* __restrict__ w3g,
                     const float* __restrict__ b3g,
                     float* __restrict__ out,
                     int E, int nNodes)
{
    extern __shared__ char dynraw[];
    __shared__ int   s_src[TILE_E], s_dst[TILE_E];
    __shared__ float s_b1[128], s_b2[64], s_w3[64];
    __shared__ float s_b3;
    __shared__ int   s_is64;
    __shared__ float s_part[TILE_E][4];

    const int tid = threadIdx.x;
    const int wid = tid >> 5;
    const int lid = tid & 31;
    const int e0  = blockIdx.x * TILE_E;
    const uint32_t sb = smem_u32(dynraw);

    // ---- setup ----
    if (tid == 0) {
        const long long* e64 = (const long long*)ei_raw;
        int ok = 1;
        #pragma unroll
        for (int i = 0; i < 8; ++i) {
            long long v = e64[i];
            if (v < 0 || v >= (long long)nNodes) { ok = 0; break; }
        }
        s_is64 = ok;
        s_b3 = b3g[0];
    }
    __syncthreads();
    {
        const int is64 = s_is64;
        if (tid < 256) {
            int t = tid & (TILE_E - 1);
            int e = e0 + t; if (e >= E) e = 0;
            int v;
            if (tid < TILE_E) {
                v = is64 ? (int)((const long long*)ei_raw)[e] : ((const int*)ei_raw)[e];
                s_src[t] = min(max(v, 0), nNodes - 1);
            } else {
                v = is64 ? (int)((const long long*)ei_raw)[(size_t)E + e]
                         : ((const int*)ei_raw)[(size_t)E + e];
                s_dst[t] = min(max(v, 0), nNodes - 1);
            }
        } else if (tid < 384) {
            s_b1[tid - 256] = b1g[tid - 256];
        } else if (tid < 448) {
            s_b2[tid - 384] = b2g[tid - 384];
        } else {
            s_w3[tid - 448] = w3g[tid - 448];
        }
    }
    __syncthreads();

    const uint32_t lrow = (uint32_t)(lid & 15);
    const uint32_t lcol = (uint32_t)(lid >> 4) * 8;

    const bool is_producer = (wid >= 8);

    // ======================= role state =======================
    // consumer: warp tile 32 rows x 64 cols; wmC 0..3, wnC 0..1
    const int wmC = wid >> 1;
    const int wnC = wid & 1;
    float acc[2][8][4];
    #pragma unroll
    for (int a = 0; a < 2; ++a)
        #pragma unroll
        for (int b = 0; b < 8; ++b)
            #pragma unroll
            for (int d = 0; d < 4; ++d) acc[a][b][d] = 0.f;

    // producer: 16 edges per warp, held in regs across a half's 4 chunks
    const int pw = wid - 8;
    float2 vs[16], vd[16];

    // producer fill of chunk c into buf (op = c&3: 0 src, 1 dst, 2 prod, 3 diff)
    auto fill = [&](int c, uint32_t buf) {
        const int op   = c & 3;
        const int half = (c >> 2) * 64;
        const uint32_t ah = buf + B1_AH, al = buf + B1_AL;
        if (op == 0) {
            #pragma unroll
            for (int i = 0; i < 16; ++i) {
                int m = pw * 16 + i;
                vs[i] = *(const float2*)(z + (size_t)s_src[m] * HDIM + half + 2 * lid);
            }
        } else if (op == 1) {
            #pragma unroll
            for (int i = 0; i < 16; ++i) {
                int m = pw * 16 + i;
                vd[i] = *(const float2*)(z + (size_t)s_dst[m] * HDIM + half + 2 * lid);
            }
        }
        #pragma unroll
        for (int i = 0; i < 16; ++i) {
            int m = pw * 16 + i;
            float2 v;
            if (op == 0)      v = vs[i];
            else if (op == 1) v = vd[i];
            else if (op == 2) { v.x = vs[i].x * vd[i].x;        v.y = vs[i].y * vd[i].y; }
            else              { v.x = fabsf(vs[i].x - vd[i].x); v.y = fabsf(vs[i].y - vd[i].y); }
            uint32_t lo2, hi2 = split2(v.x, v.y, lo2);
            uint32_t off = (uint32_t)m * STRIDE1B + (uint32_t)lid * 4;
            STS32(ah + off, hi2);
            STS32(al + off, lo2);
        }
    };
    // producer: W1 chunk via cp.async (256 producer threads, 1024 vec loads)
    auto cpB1 = [&](int c, uint32_t buf) {
        const char* srcH = (const char*)g_W1T_h;
        const char* srcL = (const char*)g_W1T_l;
        const int ptid = pw * 32 + lid;        // 0..255
        #pragma unroll
        for (int it = 0; it < 4; ++it) {
            int idx = ptid + it * 256;         // 0..1023
            int n = idx >> 3, q = idx & 7;
            uint32_t goff = (uint32_t)n * 1024u + (uint32_t)c * 128u + (uint32_t)q * 16u;
            uint32_t soff = (uint32_t)n * STRIDE1B + (uint32_t)q * 16u;
            CP16(buf + B1_BH + soff, srcH + goff);
            CP16(buf + B1_BL + soff, srcL + goff);
        }
    };

    // ---- prologue: producers fill chunk 0 + prefetch B2; consumers idle ----
    if (is_producer) {
        // B2 prefetch (once)
        {
            const char* srcH = (const char*)g_W2T_h;
            const char* srcL = (const char*)g_W2T_l;
            const int ptid = pw * 32 + lid;
            #pragma unroll
            for (int it = 0; it < 4; ++it) {
                int idx = ptid + it * 256;     // 0..1023
                int n = idx >> 4, q = idx & 15;
                uint32_t goff = (uint32_t)n * 256u + (uint32_t)q * 16u;
                uint32_t soff = (uint32_t)n * STRIDE2B + (uint32_t)q * 16u;
                CP16(sb + G2_BH + soff, srcH + goff);
                CP16(sb + G2_BL + soff, srcL + goff);
            }
        }
        cpB1(0, sb);
        CP_COMMIT();
        fill(0, sb);
        CP_WAIT0();
    }
    __syncthreads();

    // ---- main loop: consumers MMA chunk c; producers fill chunk c+1 ----
    for (int c = 0; c < 8; ++c) {
        const uint32_t buf  = sb + (uint32_t)(c & 1) * BUF1_BYTES;
        const uint32_t nbuf = sb + (uint32_t)((c + 1) & 1) * BUF1_BYTES;
        if (is_producer) {
            if (c < 7) {
                cpB1(c + 1, nbuf);
                CP_COMMIT();
                fill(c + 1, nbuf);
                CP_WAIT0();
            }
        } else {
            const uint32_t aH = buf + B1_AH + (wmC * 32u + lrow) * STRIDE1B + lcol * 2u;
            const uint32_t aL = buf + B1_AL + (wmC * 32u + lrow) * STRIDE1B + lcol * 2u;
            const uint32_t bHb = buf + B1_BH + (wnC * 64u + lrow) * STRIDE1B + lcol * 2u;
            const uint32_t bLb = buf + B1_BL + (wnC * 64u + lrow) * STRIDE1B + lcol * 2u;
            #pragma unroll
            for (int ks = 0; ks < 4; ++ks) {
                const uint32_t ko = (uint32_t)ks * 32u;
                uint32_t ah[2][4], al[2][4];
                LDSM4(ah[0], aH + ko);
                LDSM4(ah[1], aH + ko + 16u * STRIDE1B);
                LDSM4(al[0], aL + ko);
                LDSM4(al[1], aL + ko + 16u * STRIDE1B);
                #pragma unroll
                for (int gg = 0; gg < 2; ++gg) {
                    uint32_t bh[2][4], bl[2][4];
                    #pragma unroll
                    for (int gi = 0; gi < 2; ++gi) {
                        uint32_t rb = ko + (uint32_t)(gg * 2 + gi) * 16u * STRIDE1B;
                        LDSM4(bh[gi], bHb + rb);
                        LDSM4(bl[gi], bLb + rb);
                    }
                    #pragma unroll
                    for (int fm = 0; fm < 2; ++fm)
                        #pragma unroll
                        for (int q = 0; q < 4; ++q) {
                            const int gi = q >> 1, sel = q & 1;
                            const int fn = gg * 4 + q;
                            MMA16816(acc[fm][fn], ah[fm], bh[gi][sel], bh[gi][sel + 2]);
                            MMA16816(acc[fm][fn], ah[fm], bl[gi][sel], bl[gi][sel + 2]);
                            MMA16816(acc[fm][fn], al[fm], bh[gi][sel], bh[gi][sel + 2]);
                        }
                }
            }
        }
        __syncthreads();
    }

    // ---- epilogue 1: consumers write relu(+b1)->split->A2 (buf0 overlay) ----
    if (!is_producer) {
        const uint32_t a2h = sb + G2_AH, a2l = sb + G2_AL;
        #pragma unroll
        for (int fm = 0; fm < 2; ++fm)
            #pragma unroll
            for (int fn = 0; fn < 8; ++fn) {
                const int col  = wnC * 64 + fn * 8 + (lid & 3) * 2;
                const int row0 = wmC * 32 + fm * 16 + (lid >> 2);
                float x0 = fmaxf(acc[fm][fn][0] + s_b1[col],     0.f);
                float x1 = fmaxf(acc[fm][fn][1] + s_b1[col + 1], 0.f);
                float x2 = fmaxf(acc[fm][fn][2] + s_b1[col],     0.f);
                float x3 = fmaxf(acc[fm][fn][3] + s_b1[col + 1], 0.f);
                uint32_t lo2, hi2;
                uint32_t o0 = (uint32_t)row0 * STRIDE2B + (uint32_t)col * 2;
                hi2 = split2(x0, x1, lo2);
                STS32(a2h + o0, hi2); STS32(a2l + o0, lo2);
                uint32_t o1 = o0 + 8u * STRIDE2B;
                hi2 = split2(x2, x3, lo2);
                STS32(a2h + o1, hi2); STS32(a2l + o1, lo2);
            }
    }
    __syncthreads();

    // ---- GEMM2 (all 16 warps): [128,128] x [64,128]^T, warp tile 32x16 ----
    const int wm2 = wid >> 2;      // 0..3 : 32-row band
    const int wn2 = wid & 3;       // 0..3 : 16-col band
    float acc2[2][2][4];
    #pragma unroll
    for (int a = 0; a < 2; ++a)
        #pragma unroll
        for (int b = 0; b < 2; ++b)
            #pragma unroll
            for (int d = 0; d < 4; ++d) acc2[a][b][d] = 0.f;
    {
        const uint32_t rowoff = (wm2 * 32u + lrow) * STRIDE2B + lcol * 2u;
        const uint32_t noff   = (wn2 * 16u + lrow) * STRIDE2B + lcol * 2u;
        const uint32_t a2H = sb + G2_AH + rowoff;
        const uint32_t a2L = sb + G2_AL + rowoff;
        const uint32_t b2H = sb + G2_BH + noff;
        const uint32_t b2L = sb + G2_BL + noff;
        #pragma unroll
        for (int ks = 0; ks < 8; ++ks) {
            const uint32_t ko = (uint32_t)ks * 32u;
            uint32_t ah[2][4], al[2][4], bh[4], bl[4];
            LDSM4(ah[0], a2H + ko);
            LDSM4(ah[1], a2H + ko + 16u * STRIDE2B);
            LDSM4(al[0], a2L + ko);
            LDSM4(al[1], a2L + ko + 16u * STRIDE2B);
            LDSM4(bh, b2H + ko);
            LDSM4(bl, b2L + ko);
            #pragma unroll
            for (int fm = 0; fm < 2; ++fm)
                #pragma unroll
                for (int fn = 0; fn < 2; ++fn) {
                    MMA16816(acc2[fm][fn], ah[fm], bh[fn], bh[fn + 2]);
                    MMA16816(acc2[fm][fn], ah[fm], bl[fn], bl[fn + 2]);
                    MMA16816(acc2[fm][fn], al[fm], bh[fn], bh[fn + 2]);
                }
        }
    }

    // ---- epilogue 2: relu(+b2), dot w3, quad-reduce, cross-band add ----
    #pragma unroll
    for (int fm = 0; fm < 2; ++fm)
        #pragma unroll
        for (int rh = 0; rh < 2; ++rh) {
            float s = 0.f;
            #pragma unroll
            for (int fn = 0; fn < 2; ++fn) {
                const int col = wn2 * 16 + fn * 8 + (lid & 3) * 2;
                float h0 = fmaxf(acc2[fm][fn][rh * 2 + 0] + s_b2[col],     0.f);
                float h1 = fmaxf(acc2[fm][fn][rh * 2 + 1] + s_b2[col + 1], 0.f);
                s = fmaf(h0, s_w3[col], fmaf(h1, s_w3[col + 1], s));
            }
            s += __shfl_xor_sync(0xffffffffu, s, 1);
            s += __shfl_xor_sync(0xffffffffu, s, 2);
            if ((lid & 3) == 0)
                s_part[wm2 * 32 + fm * 16 + rh * 8 + (lid >> 2)][wn2] = s;
        }
    __syncthreads();
    if (tid < TILE_E) {
        int e = e0 + tid;
        if (e < E)
            out[e] = s_part[tid][0] + s_part[tid][1]
                   + s_part[tid][2] + s_part[tid][3] + s_b3;
    }
}

extern "C" void kernel_launch(void* const* d_in, const int* in_sizes, int n_in,
                              void* d_out, int out_size) {
    const float* z  = (const float*)d_in[0];
    const void*  ei = d_in[1];
    const float* W1 = (const float*)d_in[2];
    const float* b1 = (const float*)d_in[3];
    const float* W2 = (const float*)d_in[4];
    const float* b2 = (const float*)d_in[5];
    const float* W3 = (const float*)d_in[6];
    const float* b3 = (const float*)d_in[7];
    float* out = (float*)d_out;

    const int E      = out_size;
    const int nNodes = in_sizes[0] / HDIM;

    prep_kernel<<<256, 256>>>(W1, W2);

    cudaFuncSetAttribute(link_mma_kernel,
                         cudaFuncAttributeMaxDynamicSharedMemorySize, SMEM_DYN);
    const int grid = (E + TILE_E - 1) / TILE_E;
    link_mma_kernel<<<grid, NTHREADS, SMEM_DYN>>>(z, ei, b1, b2, W3, b3,
                                                  out, E, nNodes);
}

// round 9
// speedup vs baseline: 2.0065x; 1.4621x over previous
#include <cuda_runtime.h>
#include <cuda_fp16.h>
#include <cstdint>
#include <math.h>

#define TILE_E   128
#define NTHREADS 512
#define HDIM     128
#define STRIDE1B 144   // bytes/row, GEMM1 tiles (36 words -> conflict-free ldsm)
#define STRIDE2B 272   // bytes/row, GEMM2 tiles (68 words -> conflict-free ldsm)

// ---------------- global scratch: transposed + hi/lo split fp16 weights ----------------
// W1T chunk-reordered: new_k = c*64 + j ; orig_k = (c&3)*128 + (c>>2)*64 + j
__device__ __half g_W1T_h[128 * 512];   // [n][new_k] hi
__device__ __half g_W1T_l[128 * 512];   // residual lo
__device__ __half g_W2T_h[64 * 128];    // [n][k]
__device__ __half g_W2T_l[64 * 128];

__global__ void prep_kernel(const float* __restrict__ W1, const float* __restrict__ W2) {
    int i = blockIdx.x * blockDim.x + threadIdx.x;
    if (i < 128 * 512) {
        int n = i >> 9, nk = i & 511;
        int c = nk >> 6, j = nk & 63;
        int orig_k = (c & 3) * 128 + (c >> 2) * 64 + j;
        float x = W1[orig_k * 128 + n];
        __half h = __float2half_rn(x);
        g_W1T_h[i] = h;
        g_W1T_l[i] = __float2half_rn(x - __half2float(h));
    }
    if (i < 64 * 128) {
        int n = i >> 7, k = i & 127;
        float x = W2[k * 64 + n];
        __half h = __float2half_rn(x);
        g_W2T_h[i] = h;
        g_W2T_l[i] = __float2half_rn(x - __half2float(h));
    }
}

// ---------------- helpers ----------------
__device__ __forceinline__ uint32_t smem_u32(const void* p) {
    uint32_t a;
    asm("{ .reg .u64 t; cvta.to.shared.u64 t, %1; cvt.u32.u64 %0, t; }" : "=r"(a) : "l"(p));
    return a;
}
#define STS32(addr, v) \
    asm volatile("st.shared.b32 [%0], %1;" :: "r"(addr), "r"(v) : "memory")
#define CP16(saddr, gaddr) \
    asm volatile("cp.async.cg.shared.global [%0], [%1], 16;" \
        :: "r"(saddr), "l"(gaddr) : "memory")
#define CP_COMMIT() asm volatile("cp.async.commit_group;" ::: "memory")
#define CP_WAIT0()  asm volatile("cp.async.wait_group 0;" ::: "memory")
#define LDSM4(r, a) \
    asm volatile("ldmatrix.sync.aligned.m8n8.x4.shared.b16 {%0,%1,%2,%3}, [%4];" \
        : "=r"((r)[0]), "=r"((r)[1]), "=r"((r)[2]), "=r"((r)[3]) : "r"(a))
#define MMAF16(c, a, b0v, b1v) \
    asm volatile("mma.sync.aligned.m16n8k16.row.col.f32.f16.f16.f32 " \
        "{%0,%1,%2,%3}, {%4,%5,%6,%7}, {%8,%9}, {%0,%1,%2,%3};" \
        : "+f"((c)[0]), "+f"((c)[1]), "+f"((c)[2]), "+f"((c)[3]) \
        : "r"((a)[0]), "r"((a)[1]), "r"((a)[2]), "r"((a)[3]), "r"(b0v), "r"(b1v))

// pack (x0 -> lo half, x1 -> hi half) as f16x2
__device__ __forceinline__ uint32_t packh2(float x0, float x1) {
    uint32_t r;
    asm("cvt.rn.f16x2.f32 %0, %1, %2;" : "=r"(r) : "f"(x1), "f"(x0));
    return r;
}

// GEMM1 double-buffer (per half): A (single fp16) | B hi | B lo  (each 128x144B)
#define B1_A  0
#define B1_BH 18432
#define B1_BL 36864
#define BUF1_BYTES 55296
// GEMM2: A2 overlays buf0; B2 dedicated (prefetched once)
#define G2_A  0               // 128 x 272B = 34816 (fits in buf0's 55296)
#define G2_BH 110592          // 64 x 272B = 17408
#define G2_BL 128000
#define SMEM_DYN 145408

__global__ __launch_bounds__(NTHREADS, 1)
void link_mma_kernel(const float* __restrict__ z,
                     const void* __restrict__ ei_raw,
                     const float* __restrict__ b1g,
                     const float* __restrict__ b2g,
                     const float* __restrict__ w3g,
                     const float* __restrict__ b3g,
                     float* __restrict__ out,
                     int E, int nNodes)
{
    extern __shared__ char dynraw[];
    __shared__ int   s_src[TILE_E], s_dst[TILE_E];
    __shared__ float s_b1[128], s_b2[64], s_w3[64];
    __shared__ float s_b3;
    __shared__ int   s_is64;
    __shared__ float s_part[TILE_E][4];

    const int tid = threadIdx.x;
    const int wid = tid >> 5;
    const int lid = tid & 31;
    const int e0  = blockIdx.x * TILE_E;
    const uint32_t sb = smem_u32(dynraw);

    // ---- setup ----
    if (tid == 0) {
        const long long* e64 = (const long long*)ei_raw;
        int ok = 1;
        #pragma unroll
        for (int i = 0; i < 8; ++i) {
            long long v = e64[i];
            if (v < 0 || v >= (long long)nNodes) { ok = 0; break; }
        }
        s_is64 = ok;
        s_b3 = b3g[0];
    }
    __syncthreads();
    {
        const int is64 = s_is64;
        if (tid < 256) {
            int t = tid & (TILE_E - 1);
            int e = e0 + t; if (e >= E) e = 0;
            int v;
            if (tid < TILE_E) {
                v = is64 ? (int)((const long long*)ei_raw)[e] : ((const int*)ei_raw)[e];
                s_src[t] = min(max(v, 0), nNodes - 1);
            } else {
                v = is64 ? (int)((const long long*)ei_raw)[(size_t)E + e]
                         : ((const int*)ei_raw)[(size_t)E + e];
                s_dst[t] = min(max(v, 0), nNodes - 1);
            }
        } else if (tid < 384) {
            s_b1[tid - 256] = b1g[tid - 256];
        } else if (tid < 448) {
            s_b2[tid - 384] = b2g[tid - 384];
        } else {
            s_w3[tid - 448] = w3g[tid - 448];
        }
    }
    __syncthreads();

    const uint32_t lrow = (uint32_t)(lid & 15);
    const uint32_t lcol = (uint32_t)(lid >> 4) * 8;
    const bool is_producer = (wid >= 8);

    // consumer: warp tile 32 rows x 64 cols
    const int wmC = wid >> 1;
    const int wnC = wid & 1;
    float acc[2][8][4];
    #pragma unroll
    for (int a = 0; a < 2; ++a)
        #pragma unroll
        for (int b = 0; b < 8; ++b)
            #pragma unroll
            for (int d = 0; d < 4; ++d) acc[a][b][d] = 0.f;

    // producer: 16 edges per warp, z halves held in regs across 4 chunks
    const int pw = wid - 8;
    float2 vs[16], vd[16];

    auto fill = [&](int c, uint32_t buf) {
        const int op   = c & 3;              // 0 src, 1 dst, 2 prod, 3 diff
        const int half = (c >> 2) * 64;
        const uint32_t aT = buf + B1_A;
        if (op == 0) {
            #pragma unroll
            for (int i = 0; i < 16; ++i) {
                int m = pw * 16 + i;
                vs[i] = *(const float2*)(z + (size_t)s_src[m] * HDIM + half + 2 * lid);
            }
        } else if (op == 1) {
            #pragma unroll
            for (int i = 0; i < 16; ++i) {
                int m = pw * 16 + i;
                vd[i] = *(const float2*)(z + (size_t)s_dst[m] * HDIM + half + 2 * lid);
            }
        }
        #pragma unroll
        for (int i = 0; i < 16; ++i) {
            int m = pw * 16 + i;
            float2 v;
            if (op == 0)      v = vs[i];
            else if (op == 1) v = vd[i];
            else if (op == 2) { v.x = vs[i].x * vd[i].x;        v.y = vs[i].y * vd[i].y; }
            else              { v.x = fabsf(vs[i].x - vd[i].x); v.y = fabsf(vs[i].y - vd[i].y); }
            STS32(aT + (uint32_t)m * STRIDE1B + (uint32_t)lid * 4, packh2(v.x, v.y));
        }
    };
    auto cpB1 = [&](int c, uint32_t buf) {
        const char* srcH = (const char*)g_W1T_h;
        const char* srcL = (const char*)g_W1T_l;
        const int ptid = pw * 32 + lid;        // 0..255
        #pragma unroll
        for (int it = 0; it < 4; ++it) {
            int idx = ptid + it * 256;         // 0..1023
            int n = idx >> 3, q = idx & 7;
            uint32_t goff = (uint32_t)n * 1024u + (uint32_t)c * 128u + (uint32_t)q * 16u;
            uint32_t soff = (uint32_t)n * STRIDE1B + (uint32_t)q * 16u;
            CP16(buf + B1_BH + soff, srcH + goff);
            CP16(buf + B1_BL + soff, srcL + goff);
        }
    };

    // ---- prologue ----
    if (is_producer) {
        {   // B2 prefetch (once)
            const char* srcH = (const char*)g_W2T_h;
            const char* srcL = (const char*)g_W2T_l;
            const int ptid = pw * 32 + lid;
            #pragma unroll
            for (int it = 0; it < 4; ++it) {
                int idx = ptid + it * 256;     // 0..1023
                int n = idx >> 4, q = idx & 15;
                uint32_t goff = (uint32_t)n * 256u + (uint32_t)q * 16u;
                uint32_t soff = (uint32_t)n * STRIDE2B + (uint32_t)q * 16u;
                CP16(sb + G2_BH + soff, srcH + goff);
                CP16(sb + G2_BL + soff, srcL + goff);
            }
        }
        cpB1(0, sb);
        CP_COMMIT();
        fill(0, sb);
        CP_WAIT0();
    }
    __syncthreads();

    // ---- main loop: consumers MMA chunk c; producers fill chunk c+1 ----
    for (int c = 0; c < 8; ++c) {
        const uint32_t buf  = sb + (uint32_t)(c & 1) * BUF1_BYTES;
        const uint32_t nbuf = sb + (uint32_t)((c + 1) & 1) * BUF1_BYTES;
        if (is_producer) {
            if (c < 7) {
                cpB1(c + 1, nbuf);
                CP_COMMIT();
                fill(c + 1, nbuf);
                CP_WAIT0();
            }
        } else {
            const uint32_t aT  = buf + B1_A  + (wmC * 32u + lrow) * STRIDE1B + lcol * 2u;
            const uint32_t bHb = buf + B1_BH + (wnC * 64u + lrow) * STRIDE1B + lcol * 2u;
            const uint32_t bLb = buf + B1_BL + (wnC * 64u + lrow) * STRIDE1B + lcol * 2u;
            #pragma unroll
            for (int ks = 0; ks < 4; ++ks) {
                const uint32_t ko = (uint32_t)ks * 32u;
                uint32_t a[2][4];
                LDSM4(a[0], aT + ko);
                LDSM4(a[1], aT + ko + 16u * STRIDE1B);
                #pragma unroll
                for (int gg = 0; gg < 2; ++gg) {
                    uint32_t bh[2][4], bl[2][4];
                    #pragma unroll
                    for (int gi = 0; gi < 2; ++gi) {
                        uint32_t rb = ko + (uint32_t)(gg * 2 + gi) * 16u * STRIDE1B;
                        LDSM4(bh[gi], bHb + rb);
                        LDSM4(bl[gi], bLb + rb);
                    }
                    #pragma unroll
                    for (int fm = 0; fm < 2; ++fm)
                        #pragma unroll
                        for (int q = 0; q < 4; ++q) {
                            const int gi = q >> 1, sel = q & 1;
                            const int fn = gg * 4 + q;
                            MMAF16(acc[fm][fn], a[fm], bh[gi][sel], bh[gi][sel + 2]);
                            MMAF16(acc[fm][fn], a[fm], bl[gi][sel], bl[gi][sel + 2]);
                        }
                }
            }
        }
        __syncthreads();
    }

    // ---- epilogue 1: consumers: relu(+b1) -> fp16 -> A2 (buf0 overlay) ----
    if (!is_producer) {
        const uint32_t a2 = sb + G2_A;
        #pragma unroll
        for (int fm = 0; fm < 2; ++fm)
            #pragma unroll
            for (int fn = 0; fn < 8; ++fn) {
                const int col  = wnC * 64 + fn * 8 + (lid & 3) * 2;
                const int row0 = wmC * 32 + fm * 16 + (lid >> 2);
                float x0 = fmaxf(acc[fm][fn][0] + s_b1[col],     0.f);
                float x1 = fmaxf(acc[fm][fn][1] + s_b1[col + 1], 0.f);
                float x2 = fmaxf(acc[fm][fn][2] + s_b1[col],     0.f);
                float x3 = fmaxf(acc[fm][fn][3] + s_b1[col + 1], 0.f);
                uint32_t o0 = (uint32_t)row0 * STRIDE2B + (uint32_t)col * 2;
                STS32(a2 + o0, packh2(x0, x1));
                STS32(a2 + o0 + 8u * STRIDE2B, packh2(x2, x3));
            }
    }
    __syncthreads();

    // ---- GEMM2 (all 16 warps): [128,128] x [64,128]^T, warp tile 32x16 ----
    const int wm2 = wid >> 2;
    const int wn2 = wid & 3;
    float acc2[2][2][4];
    #pragma unroll
    for (int a = 0; a < 2; ++a)
        #pragma unroll
        for (int b = 0; b < 2; ++b)
            #pragma unroll
            for (int d = 0; d < 4; ++d) acc2[a][b][d] = 0.f;
    {
        const uint32_t a2T = sb + G2_A  + (wm2 * 32u + lrow) * STRIDE2B + lcol * 2u;
        const uint32_t b2H = sb + G2_BH + (wn2 * 16u + lrow) * STRIDE2B + lcol * 2u;
        const uint32_t b2L = sb + G2_BL + (wn2 * 16u + lrow) * STRIDE2B + lcol * 2u;
        #pragma unroll
        for (int ks = 0; ks < 8; ++ks) {
            const uint32_t ko = (uint32_t)ks * 32u;
            uint32_t a[2][4], bh[4], bl[4];
            LDSM4(a[0], a2T + ko);
            LDSM4(a[1], a2T + ko + 16u * STRIDE2B);
            LDSM4(bh, b2H + ko);
            LDSM4(bl, b2L + ko);
            #pragma unroll
            for (int fm = 0; fm < 2; ++fm)
                #pragma unroll
                for (int fn = 0; fn < 2; ++fn) {
                    MMAF16(acc2[fm][fn], a[fm], bh[fn], bh[fn + 2]);
                    MMAF16(acc2[fm][fn], a[fm], bl[fn], bl[fn + 2]);
                }
        }
    }

    // ---- epilogue 2: relu(+b2), dot w3, quad-reduce, cross-band add ----
    #pragma unroll
    for (int fm = 0; fm < 2; ++fm)
        #pragma unroll
        for (int rh = 0; rh < 2; ++rh) {
            float s = 0.f;
            #pragma unroll
            for (int fn = 0; fn < 2; ++fn) {
                const int col = wn2 * 16 + fn * 8 + (lid & 3) * 2;
                float h0 = fmaxf(acc2[fm][fn][rh * 2 + 0] + s_b2[col],     0.f);
                float h1 = fmaxf(acc2[fm][fn][rh * 2 + 1] + s_b2[col + 1], 0.f);
                s = fmaf(h0, s_w3[col], fmaf(h1, s_w3[col + 1], s));
            }
            s += __shfl_xor_sync(0xffffffffu, s, 1);
            s += __shfl_xor_sync(0xffffffffu, s, 2);
            if ((lid & 3) == 0)
                s_part[wm2 * 32 + fm * 16 + rh * 8 + (lid >> 2)][wn2] = s;
        }
    __syncthreads();
    if (tid < TILE_E) {
        int e = e0 + tid;
        if (e < E)
            out[e] = s_part[tid][0] + s_part[tid][1]
                   + s_part[tid][2] + s_part[tid][3] + s_b3;
    }
}

extern "C" void kernel_launch(void* const* d_in, const int* in_sizes, int n_in,
                              void* d_out, int out_size) {
    const float* z  = (const float*)d_in[0];
    const void*  ei = d_in[1];
    const float* W1 = (const float*)d_in[2];
    const float* b1 = (const float*)d_in[3];
    const float* W2 = (const float*)d_in[4];
    const float* b2 = (const float*)d_in[5];
    const float* W3 = (const float*)d_in[6];
    const float* b3 = (const float*)d_in[7];
    float* out = (float*)d_out;

    const int E      = out_size;
    const int nNodes = in_sizes[0] / HDIM;

    prep_kernel<<<256, 256>>>(W1, W2);

    cudaFuncSetAttribute(link_mma_kernel,
                         cudaFuncAttributeMaxDynamicSharedMemorySize, SMEM_DYN);
    const int grid = (E + TILE_E - 1) / TILE_E;
    link_mma_kernel<<<grid, NTHREADS, SMEM_DYN>>>(z, ei, b1, b2, W3, b3,
                                                  out, E, nNodes);
}

// round 10
// speedup vs baseline: 2.6283x; 1.3099x over previous
#include <cuda_runtime.h>
#include <cuda_fp16.h>
#include <cstdint>
#include <math.h>

#define TILE_E   128
#define NTHREADS 512
#define HDIM     128
#define STRIDE1B 144   // bytes/row, GEMM1 tiles (36 words -> conflict-free ldsm)
#define STRIDE2B 272   // bytes/row, GEMM2 tiles (68 words -> conflict-free ldsm)

// ---------------- global scratch: transposed fp16 weights ----------------
// W1T chunk-reordered: new_k = c*64 + j ; orig_k = (c&3)*128 + (c>>2)*64 + j
__device__ __half g_W1T[128 * 512];   // [n][new_k]
__device__ __half g_W2T[64 * 128];    // [n][k]

__global__ void prep_kernel(const float* __restrict__ W1, const float* __restrict__ W2) {
    int i = blockIdx.x * blockDim.x + threadIdx.x;
    if (i < 128 * 512) {
        int n = i >> 9, nk = i & 511;
        int c = nk >> 6, j = nk & 63;
        int orig_k = (c & 3) * 128 + (c >> 2) * 64 + j;
        g_W1T[i] = __float2half_rn(W1[orig_k * 128 + n]);
    }
    if (i < 64 * 128) {
        int n = i >> 7, k = i & 127;
        g_W2T[i] = __float2half_rn(W2[k * 64 + n]);
    }
}

// ---------------- helpers ----------------
__device__ __forceinline__ uint32_t smem_u32(const void* p) {
    uint32_t a;
    asm("{ .reg .u64 t; cvta.to.shared.u64 t, %1; cvt.u32.u64 %0, t; }" : "=r"(a) : "l"(p));
    return a;
}
#define STS32(addr, v) \
    asm volatile("st.shared.b32 [%0], %1;" :: "r"(addr), "r"(v) : "memory")
#define CP16(saddr, gaddr) \
    asm volatile("cp.async.cg.shared.global [%0], [%1], 16;" \
        :: "r"(saddr), "l"(gaddr) : "memory")
#define CP_COMMIT() asm volatile("cp.async.commit_group;" ::: "memory")
#define CP_WAIT0()  asm volatile("cp.async.wait_group 0;" ::: "memory")
#define LDSM4(r, a) \
    asm volatile("ldmatrix.sync.aligned.m8n8.x4.shared.b16 {%0,%1,%2,%3}, [%4];" \
        : "=r"((r)[0]), "=r"((r)[1]), "=r"((r)[2]), "=r"((r)[3]) : "r"(a))
#define MMAF16(c, a, b0v, b1v) \
    asm volatile("mma.sync.aligned.m16n8k16.row.col.f32.f16.f16.f32 " \
        "{%0,%1,%2,%3}, {%4,%5,%6,%7}, {%8,%9}, {%0,%1,%2,%3};" \
        : "+f"((c)[0]), "+f"((c)[1]), "+f"((c)[2]), "+f"((c)[3]) \
        : "r"((a)[0]), "r"((a)[1]), "r"((a)[2]), "r"((a)[3]), "r"(b0v), "r"(b1v))

__device__ __forceinline__ uint32_t packh2(float x0, float x1) {
    uint32_t r;
    asm("cvt.rn.f16x2.f32 %0, %1, %2;" : "=r"(r) : "f"(x1), "f"(x0));
    return r;
}

// GEMM1 double-buffer (per half): A fp16 | B fp16  (each 128x144B)
#define B1_A  0
#define B1_B  18432
#define BUF1_BYTES 36864
// GEMM2: A2 overlays buf0 (34816 <= 36864); B2 dedicated (prefetched once)
#define G2_A  0
#define G2_B  73728            // 64 x 272B = 17408
#define SMEM_DYN 91136

__global__ __launch_bounds__(NTHREADS, 1)
void link_mma_kernel(const float* __restrict__ z,
                     const void* __restrict__ ei_raw,
                     const float* __restrict__ b1g,
                     const float* __restrict__ b2g,
                     const float* __restrict__ w3g,
                     const float* __restrict__ b3g,
                     float* __restrict__ out,
                     int E, int nNodes)
{
    extern __shared__ char dynraw[];
    __shared__ int   s_src[TILE_E], s_dst[TILE_E];
    __shared__ float s_b1[128], s_b2[64], s_w3[64];
    __shared__ float s_b3;
    __shared__ int   s_is64;
    __shared__ float s_part[TILE_E][4];

    const int tid = threadIdx.x;
    const int wid = tid >> 5;
    const int lid = tid & 31;
    const int e0  = blockIdx.x * TILE_E;
    const uint32_t sb = smem_u32(dynraw);

    // ---- setup ----
    if (tid == 0) {
        const long long* e64 = (const long long*)ei_raw;
        int ok = 1;
        #pragma unroll
        for (int i = 0; i < 8; ++i) {
            long long v = e64[i];
            if (v < 0 || v >= (long long)nNodes) { ok = 0; break; }
        }
        s_is64 = ok;
        s_b3 = b3g[0];
    }
    __syncthreads();
    {
        const int is64 = s_is64;
        if (tid < 256) {
            int t = tid & (TILE_E - 1);
            int e = e0 + t; if (e >= E) e = 0;
            int v;
            if (tid < TILE_E) {
                v = is64 ? (int)((const long long*)ei_raw)[e] : ((const int*)ei_raw)[e];
                s_src[t] = min(max(v, 0), nNodes - 1);
            } else {
                v = is64 ? (int)((const long long*)ei_raw)[(size_t)E + e]
                         : ((const int*)ei_raw)[(size_t)E + e];
                s_dst[t] = min(max(v, 0), nNodes - 1);
            }
        } else if (tid < 384) {
            s_b1[tid - 256] = b1g[tid - 256];
        } else if (tid < 448) {
            s_b2[tid - 384] = b2g[tid - 384];
        } else {
            s_w3[tid - 448] = w3g[tid - 448];
        }
    }
    __syncthreads();

    const uint32_t lrow = (uint32_t)(lid & 15);
    const uint32_t lcol = (uint32_t)(lid >> 4) * 8;
    const bool is_producer = (wid >= 8);

    // consumer: warp tile 32 rows x 64 cols
    const int wmC = wid >> 1;
    const int wnC = wid & 1;
    float acc[2][8][4];
    #pragma unroll
    for (int a = 0; a < 2; ++a)
        #pragma unroll
        for (int b = 0; b < 8; ++b)
            #pragma unroll
            for (int d = 0; d < 4; ++d) acc[a][b][d] = 0.f;

    // producer: 16 edges per warp, z halves held in regs across 4 chunks
    const int pw = wid - 8;
    float2 vs[16], vd[16];

    auto fill = [&](int c, uint32_t buf) {
        const int op   = c & 3;              // 0 src, 1 dst, 2 prod, 3 diff
        const int half = (c >> 2) * 64;
        const uint32_t aT = buf + B1_A;
        if (op == 0) {
            #pragma unroll
            for (int i = 0; i < 16; ++i) {
                int m = pw * 16 + i;
                vs[i] = *(const float2*)(z + (size_t)s_src[m] * HDIM + half + 2 * lid);
            }
        } else if (op == 1) {
            #pragma unroll
            for (int i = 0; i < 16; ++i) {
                int m = pw * 16 + i;
                vd[i] = *(const float2*)(z + (size_t)s_dst[m] * HDIM + half + 2 * lid);
            }
        }
        #pragma unroll
        for (int i = 0; i < 16; ++i) {
            int m = pw * 16 + i;
            float2 v;
            if (op == 0)      v = vs[i];
            else if (op == 1) v = vd[i];
            else if (op == 2) { v.x = vs[i].x * vd[i].x;        v.y = vs[i].y * vd[i].y; }
            else              { v.x = fabsf(vs[i].x - vd[i].x); v.y = fabsf(vs[i].y - vd[i].y); }
            STS32(aT + (uint32_t)m * STRIDE1B + (uint32_t)lid * 4, packh2(v.x, v.y));
        }
    };
    auto cpB1 = [&](int c, uint32_t buf) {
        const char* src = (const char*)g_W1T;
        const int ptid = pw * 32 + lid;        // 0..255
        #pragma unroll
        for (int it = 0; it < 4; ++it) {
            int idx = ptid + it * 256;         // 0..1023
            int n = idx >> 3, q = idx & 7;
            uint32_t goff = (uint32_t)n * 1024u + (uint32_t)c * 128u + (uint32_t)q * 16u;
            uint32_t soff = (uint32_t)n * STRIDE1B + (uint32_t)q * 16u;
            CP16(buf + B1_B + soff, src + goff);
        }
    };

    // ---- prologue ----
    if (is_producer) {
        {   // B2 prefetch (once)
            const char* src = (const char*)g_W2T;
            const int ptid = pw * 32 + lid;
            #pragma unroll
            for (int it = 0; it < 4; ++it) {
                int idx = ptid + it * 256;     // 0..1023
                int n = idx >> 4, q = idx & 15;
                uint32_t goff = (uint32_t)n * 256u + (uint32_t)q * 16u;
                uint32_t soff = (uint32_t)n * STRIDE2B + (uint32_t)q * 16u;
                if (q < 16) CP16(sb + G2_B + soff, src + goff);
            }
        }
        cpB1(0, sb);
        CP_COMMIT();
        fill(0, sb);
        CP_WAIT0();
    }
    __syncthreads();

    // ---- main loop: consumers MMA chunk c; producers fill chunk c+1 ----
    for (int c = 0; c < 8; ++c) {
        const uint32_t buf  = sb + (uint32_t)(c & 1) * BUF1_BYTES;
        const uint32_t nbuf = sb + (uint32_t)((c + 1) & 1) * BUF1_BYTES;
        if (is_producer) {
            if (c < 7) {
                cpB1(c + 1, nbuf);
                CP_COMMIT();
                fill(c + 1, nbuf);
                CP_WAIT0();
            }
        } else {
            const uint32_t aT = buf + B1_A + (wmC * 32u + lrow) * STRIDE1B + lcol * 2u;
            const uint32_t bT = buf + B1_B + (wnC * 64u + lrow) * STRIDE1B + lcol * 2u;
            #pragma unroll
            for (int ks = 0; ks < 4; ++ks) {
                const uint32_t ko = (uint32_t)ks * 32u;
                uint32_t a[2][4];
                LDSM4(a[0], aT + ko);
                LDSM4(a[1], aT + ko + 16u * STRIDE1B);
                #pragma unroll
                for (int gg = 0; gg < 2; ++gg) {
                    uint32_t b[2][4];
                    #pragma unroll
                    for (int gi = 0; gi < 2; ++gi) {
                        uint32_t rb = ko + (uint32_t)(gg * 2 + gi) * 16u * STRIDE1B;
                        LDSM4(b[gi], bT + rb);
                    }
                    #pragma unroll
                    for (int fm = 0; fm < 2; ++fm)
                        #pragma unroll
                        for (int q = 0; q < 4; ++q) {
                            const int gi = q >> 1, sel = q & 1;
                            const int fn = gg * 4 + q;
                            MMAF16(acc[fm][fn], a[fm], b[gi][sel], b[gi][sel + 2]);
                        }
                }
            }
        }
        __syncthreads();
    }

    // ---- epilogue 1: consumers: relu(+b1) -> fp16 -> A2 (buf0 overlay) ----
    if (!is_producer) {
        const uint32_t a2 = sb + G2_A;
        #pragma unroll
        for (int fm = 0; fm < 2; ++fm)
            #pragma unroll
            for (int fn = 0; fn < 8; ++fn) {
                const int col  = wnC * 64 + fn * 8 + (lid & 3) * 2;
                const int row0 = wmC * 32 + fm * 16 + (lid >> 2);
                float x0 = fmaxf(acc[fm][fn][0] + s_b1[col],     0.f);
                float x1 = fmaxf(acc[fm][fn][1] + s_b1[col + 1], 0.f);
                float x2 = fmaxf(acc[fm][fn][2] + s_b1[col],     0.f);
                float x3 = fmaxf(acc[fm][fn][3] + s_b1[col + 1], 0.f);
                uint32_t o0 = (uint32_t)row0 * STRIDE2B + (uint32_t)col * 2;
                STS32(a2 + o0, packh2(x0, x1));
                STS32(a2 + o0 + 8u * STRIDE2B, packh2(x2, x3));
            }
    }
    __syncthreads();

    // ---- GEMM2 (all 16 warps): [128,128] x [64,128]^T, warp tile 32x16 ----
    const int wm2 = wid >> 2;
    const int wn2 = wid & 3;
    float acc2[2][2][4];
    #pragma unroll
    for (int a = 0; a < 2; ++a)
        #pragma unroll
        for (int b = 0; b < 2; ++b)
            #pragma unroll
            for (int d = 0; d < 4; ++d) acc2[a][b][d] = 0.f;
    {
        const uint32_t a2T = sb + G2_A + (wm2 * 32u + lrow) * STRIDE2B + lcol * 2u;
        const uint32_t b2T = sb + G2_B + (wn2 * 16u + lrow) * STRIDE2B + lcol * 2u;
        #pragma unroll
        for (int ks = 0; ks < 8; ++ks) {
            const uint32_t ko = (uint32_t)ks * 32u;
            uint32_t a[2][4], b[4];
            LDSM4(a[0], a2T + ko);
            LDSM4(a[1], a2T + ko + 16u * STRIDE2B);
            LDSM4(b, b2T + ko);
            #pragma unroll
            for (int fm = 0; fm < 2; ++fm)
                #pragma unroll
                for (int fn = 0; fn < 2; ++fn)
                    MMAF16(acc2[fm][fn], a[fm], b[fn], b[fn + 2]);
        }
    }

    // ---- epilogue 2: relu(+b2), dot w3, quad-reduce, cross-band add ----
    #pragma unroll
    for (int fm = 0; fm < 2; ++fm)
        #pragma unroll
        for (int rh = 0; rh < 2; ++rh) {
            float s = 0.f;
            #pragma unroll
            for (int fn = 0; fn < 2; ++fn) {
                const int col = wn2 * 16 + fn * 8 + (lid & 3) * 2;
                float h0 = fmaxf(acc2[fm][fn][rh * 2 + 0] + s_b2[col],     0.f);
                float h1 = fmaxf(acc2[fm][fn][rh * 2 + 1] + s_b2[col + 1], 0.f);
                s = fmaf(h0, s_w3[col], fmaf(h1, s_w3[col + 1], s));
            }
            s += __shfl_xor_sync(0xffffffffu, s, 1);
            s += __shfl_xor_sync(0xffffffffu, s, 2);
            if ((lid & 3) == 0)
                s_part[wm2 * 32 + fm * 16 + rh * 8 + (lid >> 2)][wn2] = s;
        }
    __syncthreads();
    if (tid < TILE_E) {
        int e = e0 + tid;
        if (e < E)
            out[e] = s_part[tid][0] + s_part[tid][1]
                   + s_part[tid][2] + s_part[tid][3] + s_b3;
    }
}

extern "C" void kernel_launch(void* const* d_in, const int* in_sizes, int n_in,
                              void* d_out, int out_size) {
    const float* z  = (const float*)d_in[0];
    const void*  ei = d_in[1];
    const float* W1 = (const float*)d_in[2];
    const float* b1 = (const float*)d_in[3];
    const float* W2 = (const float*)d_in[4];
    const float* b2 = (const float*)d_in[5];
    const float* W3 = (const float*)d_in[6];
    const float* b3 = (const float*)d_in[7];
    float* out = (float*)d_out;

    const int E      = out_size;
    const int nNodes = in_sizes[0] / HDIM;

    prep_kernel<<<256, 256>>>(W1, W2);

    cudaFuncSetAttribute(link_mma_kernel,
                         cudaFuncAttributeMaxDynamicSharedMemorySize, SMEM_DYN);
    const int grid = (E + TILE_E - 1) / TILE_E;
    link_mma_kernel<<<grid, NTHREADS, SMEM_DYN>>>(z, ei, b1, b2, W3, b3,
                                                  out, E, nNodes);
}

// round 11
// speedup vs baseline: 3.4639x; 1.3179x over previous
#include <cuda_runtime.h>
#include <cuda_fp16.h>
#include <cstdint>
#include <math.h>

#define TILE_E   128
#define NTHREADS 512
#define HDIM     128
#define AST      272   // bytes/row for all fp16 tiles (68 words -> conflict-free ldsm)

// ---------------- global scratch: transposed fp16 weights ----------------
__device__ __half g_W1T[128 * 512];   // [n][k] from W1[k][n]   (k segment-major natural)
__device__ __half g_W2T[64 * 128];    // [n][k] from W2[k][n]

__global__ void prep_kernel(const float* __restrict__ W1, const float* __restrict__ W2) {
    int i = blockIdx.x * blockDim.x + threadIdx.x;
    if (i < 128 * 512) {
        int n = i >> 9, k = i & 511;
        g_W1T[i] = __float2half_rn(W1[k * 128 + n]);
    }
    if (i < 64 * 128) {
        int n = i >> 7, k = i & 127;
        g_W2T[i] = __float2half_rn(W2[k * 64 + n]);
    }
}

// ---------------- helpers ----------------
__device__ __forceinline__ uint32_t smem_u32(const void* p) {
    uint32_t a;
    asm("{ .reg .u64 t; cvta.to.shared.u64 t, %1; cvt.u32.u64 %0, t; }" : "=r"(a) : "l"(p));
    return a;
}
#define STS64V(addr, v0, v1) \
    asm volatile("st.shared.v2.b32 [%0], {%1,%2};" :: "r"(addr), "r"(v0), "r"(v1) : "memory")
#define CP16(saddr, gaddr) \
    asm volatile("cp.async.cg.shared.global [%0], [%1], 16;" \
        :: "r"(saddr), "l"(gaddr) : "memory")
#define CP_COMMIT() asm volatile("cp.async.commit_group;" ::: "memory")
#define CP_WAIT0()  asm volatile("cp.async.wait_group 0;" ::: "memory")
#define LDSM4(r, a) \
    asm volatile("ldmatrix.sync.aligned.m8n8.x4.shared.b16 {%0,%1,%2,%3}, [%4];" \
        : "=r"((r)[0]), "=r"((r)[1]), "=r"((r)[2]), "=r"((r)[3]) : "r"(a))
#define MMAF16(c, a, b0v, b1v) \
    asm volatile("mma.sync.aligned.m16n8k16.row.col.f32.f16.f16.f32 " \
        "{%0,%1,%2,%3}, {%4,%5,%6,%7}, {%8,%9}, {%0,%1,%2,%3};" \
        : "+f"((c)[0]), "+f"((c)[1]), "+f"((c)[2]), "+f"((c)[3]) \
        : "r"((a)[0]), "r"((a)[1]), "r"((a)[2]), "r"((a)[3]), "r"(b0v), "r"(b1v))

__device__ __forceinline__ uint32_t packh2(float x0, float x1) {
    uint32_t r;
    asm("cvt.rn.f16x2.f32 %0, %1, %2;" : "=r"(r) : "f"(x1), "f"(x0));
    return r;
}

// smem layout (dynamic): 3 A regions + 2 B regions + W2 region, all 128(or 64) x 272B
#define A0_OFF 0
#define A1_OFF 34816
#define A2_OFF 69632
#define B0_OFF 104448
#define B1_OFF 139264
#define B2_OFF 174080          // 64 x 272B = 17408
#define SMEM_DYN 191488

__global__ __launch_bounds__(NTHREADS, 1)
void link_mma_kernel(const float* __restrict__ z,
                     const void* __restrict__ ei_raw,
                     const float* __restrict__ b1g,
                     const float* __restrict__ b2g,
                     const float* __restrict__ w3g,
                     const float* __restrict__ b3g,
                     float* __restrict__ out,
                     int E, int nNodes)
{
    extern __shared__ char dynraw[];
    __shared__ int   s_src[TILE_E], s_dst[TILE_E];
    __shared__ float s_b1[128], s_b2[64], s_w3[64];
    __shared__ float s_b3;
    __shared__ int   s_is64;
    __shared__ float s_part[TILE_E][4];

    const int tid = threadIdx.x;
    const int wid = tid >> 5;
    const int lid = tid & 31;
    const int e0  = blockIdx.x * TILE_E;
    const uint32_t sb = smem_u32(dynraw);

    // ---- setup ----
    if (tid == 0) {
        const long long* e64 = (const long long*)ei_raw;
        int ok = 1;
        #pragma unroll
        for (int i = 0; i < 8; ++i) {
            long long v = e64[i];
            if (v < 0 || v >= (long long)nNodes) { ok = 0; break; }
        }
        s_is64 = ok;
        s_b3 = b3g[0];
    }
    __syncthreads();
    {
        const int is64 = s_is64;
        if (tid < 256) {
            int t = tid & (TILE_E - 1);
            int e = e0 + t; if (e >= E) e = 0;
            int v;
            if (tid < TILE_E) {
                v = is64 ? (int)((const long long*)ei_raw)[e] : ((const int*)ei_raw)[e];
                s_src[t] = min(max(v, 0), nNodes - 1);
            } else {
                v = is64 ? (int)((const long long*)ei_raw)[(size_t)E + e]
                         : ((const int*)ei_raw)[(size_t)E + e];
                s_dst[t] = min(max(v, 0), nNodes - 1);
            }
        } else if (tid < 384) {
            s_b1[tid - 256] = b1g[tid - 256];
        } else if (tid < 448) {
            s_b2[tid - 384] = b2g[tid - 384];
        } else {
            s_w3[tid - 448] = w3g[tid - 448];
        }
    }
    __syncthreads();

    const uint32_t lrow = (uint32_t)(lid & 15);
    const uint32_t lcol = (uint32_t)(lid >> 4) * 8;
    const bool is_producer = (wid >= 8);
    const int wb = wid & 7;               // fill-role warp index (both halves)

    // consumer GEMM1 mapping: warp tile 32 rows x 64 cols
    const int wmC = wid >> 1;
    const int wnC = wid & 1;
    float acc[2][8][4];
    #pragma unroll
    for (int a = 0; a < 2; ++a)
        #pragma unroll
        for (int b = 0; b < 8; ++b)
            #pragma unroll
            for (int d = 0; d < 4; ++d) acc[a][b][d] = 0.f;

    // ---- fill helpers (16 edges per warp, full 128-col rows) ----
    // direct z row -> fp16 tile
    auto fill_z = [&](const int* idxs, uint32_t dstA) {
        float4 v[16];
        #pragma unroll
        for (int i = 0; i < 16; ++i) {
            int m = wb * 16 + i;
            v[i] = *(const float4*)(z + (size_t)idxs[m] * HDIM + lid * 4);
        }
        #pragma unroll
        for (int i = 0; i < 16; ++i) {
            int m = wb * 16 + i;
            STS64V(dstA + (uint32_t)m * AST + (uint32_t)lid * 8,
                   packh2(v[i].x, v[i].y), packh2(v[i].z, v[i].w));
        }
    };
    // prod (op=0) / absdiff (op=1): re-gather both rows (L2-hot), fp32 math, cvt
    auto fill_pd = [&](int op, uint32_t dstA) {
        #pragma unroll
        for (int half = 0; half < 2; ++half) {
            float4 s4[8], d4[8];
            #pragma unroll
            for (int j = 0; j < 8; ++j) {
                int m = wb * 16 + half * 8 + j;
                s4[j] = *(const float4*)(z + (size_t)s_src[m] * HDIM + lid * 4);
                d4[j] = *(const float4*)(z + (size_t)s_dst[m] * HDIM + lid * 4);
            }
            #pragma unroll
            for (int j = 0; j < 8; ++j) {
                int m = wb * 16 + half * 8 + j;
                float4 r;
                if (op == 0) {
                    r.x = s4[j].x * d4[j].x; r.y = s4[j].y * d4[j].y;
                    r.z = s4[j].z * d4[j].z; r.w = s4[j].w * d4[j].w;
                } else {
                    r.x = fabsf(s4[j].x - d4[j].x); r.y = fabsf(s4[j].y - d4[j].y);
                    r.z = fabsf(s4[j].z - d4[j].z); r.w = fabsf(s4[j].w - d4[j].w);
                }
                STS64V(dstA + (uint32_t)m * AST + (uint32_t)lid * 8,
                       packh2(r.x, r.y), packh2(r.z, r.w));
            }
        }
    };
    // W1 segment seg (128 n-rows x 128 k) -> B buffer
    auto cpB1 = [&](int seg, uint32_t buf) {
        const char* src = (const char*)g_W1T;
        const int ptid = wb * 32 + lid;        // 0..255
        #pragma unroll
        for (int it = 0; it < 8; ++it) {
            int idx = ptid + it * 256;         // 0..2047
            int n = idx >> 4, q = idx & 15;
            uint32_t goff = (uint32_t)n * 1024u + (uint32_t)seg * 256u + (uint32_t)q * 16u;
            CP16(buf + (uint32_t)n * AST + (uint32_t)q * 16u, src + goff);
        }
    };
    // consumer: one k=128 GEMM1 phase on (Abuf, Bbuf)
    auto consumer_mma = [&](uint32_t Abuf, uint32_t Bbuf) {
        const uint32_t aT = Abuf + (wmC * 32u + lrow) * AST + lcol * 2u;
        const uint32_t bT = Bbuf + (wnC * 64u + lrow) * AST + lcol * 2u;
        #pragma unroll
        for (int ks = 0; ks < 8; ++ks) {
            const uint32_t ko = (uint32_t)ks * 32u;
            uint32_t a[2][4];
            LDSM4(a[0], aT + ko);
            LDSM4(a[1], aT + ko + 16u * AST);
            #pragma unroll
            for (int gg = 0; gg < 2; ++gg) {
                uint32_t b[2][4];
                #pragma unroll
                for (int gi = 0; gi < 2; ++gi) {
                    uint32_t rb = ko + (uint32_t)(gg * 2 + gi) * 16u * AST;
                    LDSM4(b[gi], bT + rb);
                }
                #pragma unroll
                for (int fm = 0; fm < 2; ++fm)
                    #pragma unroll
                    for (int q = 0; q < 4; ++q) {
                        const int gi = q >> 1, sel = q & 1;
                        const int fn = gg * 4 + q;
                        MMAF16(acc[fm][fn], a[fm], b[gi][sel], b[gi][sel + 2]);
                    }
            }
        }
    };

    // ---- prologue: producers cp B0/B1/W2 + fill dst->A1; consumers fill src->A0 ----
    if (is_producer) {
        cpB1(0, sb + B0_OFF);
        cpB1(1, sb + B1_OFF);
        {   // W2 tiles (64 x 256B)
            const char* src = (const char*)g_W2T;
            const int ptid = wb * 32 + lid;
            #pragma unroll
            for (int it = 0; it < 4; ++it) {
                int idx = ptid + it * 256;     // 0..1023
                int n = idx >> 4, q = idx & 15;
                CP16(sb + B2_OFF + (uint32_t)n * AST + (uint32_t)q * 16u,
                     src + (uint32_t)n * 256u + (uint32_t)q * 16u);
            }
        }
        CP_COMMIT();
        fill_z(s_dst, sb + A1_OFF);
        CP_WAIT0();
    } else {
        fill_z(s_src, sb + A0_OFF);
    }
    __syncthreads();

    // ---- phase 0: MMA(src A0, W1seg0 B0) | producers: prod -> A2 ----
    if (is_producer) fill_pd(0, sb + A2_OFF);
    else             consumer_mma(sb + A0_OFF, sb + B0_OFF);
    __syncthreads();

    // ---- phase 1: MMA(dst A1, W1seg1 B1) | producers: W1seg2->B0, diff -> A0 ----
    if (is_producer) {
        cpB1(2, sb + B0_OFF);
        CP_COMMIT();
        fill_pd(1, sb + A0_OFF);
        CP_WAIT0();
    } else {
        consumer_mma(sb + A1_OFF, sb + B1_OFF);
    }
    __syncthreads();

    // ---- phase 2: MMA(prod A2, W1seg2 B0) | producers: W1seg3->B1 ----
    if (is_producer) {
        cpB1(3, sb + B1_OFF);
        CP_COMMIT();
        CP_WAIT0();
    } else {
        consumer_mma(sb + A2_OFF, sb + B0_OFF);
    }
    __syncthreads();

    // ---- phase 3: MMA(diff A0, W1seg3 B1) ----
    if (!is_producer) consumer_mma(sb + A0_OFF, sb + B1_OFF);
    __syncthreads();

    // ---- epilogue 1: consumers: relu(+b1) -> fp16 -> h1 tile in A1 ----
    if (!is_producer) {
        const uint32_t a2 = sb + A1_OFF;
        #pragma unroll
        for (int fm = 0; fm < 2; ++fm)
            #pragma unroll
            for (int fn = 0; fn < 8; ++fn) {
                const int col  = wnC * 64 + fn * 8 + (lid & 3) * 2;
                const int row0 = wmC * 32 + fm * 16 + (lid >> 2);
                float x0 = fmaxf(acc[fm][fn][0] + s_b1[col],     0.f);
                float x1 = fmaxf(acc[fm][fn][1] + s_b1[col + 1], 0.f);
                float x2 = fmaxf(acc[fm][fn][2] + s_b1[col],     0.f);
                float x3 = fmaxf(acc[fm][fn][3] + s_b1[col + 1], 0.f);
                uint32_t o0 = (uint32_t)row0 * AST + (uint32_t)col * 2;
                asm volatile("st.shared.b32 [%0], %1;" :: "r"(a2 + o0),
                             "r"(packh2(x0, x1)) : "memory");
                asm volatile("st.shared.b32 [%0], %1;" :: "r"(a2 + o0 + 8u * AST),
                             "r"(packh2(x2, x3)) : "memory");
            }
    }
    __syncthreads();

    // ---- GEMM2 (all 16 warps): [128,128] x [64,128]^T, warp tile 32x16 ----
    const int wm2 = wid >> 2;
    const int wn2 = wid & 3;
    float acc2[2][2][4];
    #pragma unroll
    for (int a = 0; a < 2; ++a)
        #pragma unroll
        for (int b = 0; b < 2; ++b)
            #pragma unroll
            for (int d = 0; d < 4; ++d) acc2[a][b][d] = 0.f;
    {
        const uint32_t a2T = sb + A1_OFF + (wm2 * 32u + lrow) * AST + lcol * 2u;
        const uint32_t b2T = sb + B2_OFF + (wn2 * 16u + lrow) * AST + lcol * 2u;
        #pragma unroll
        for (int ks = 0; ks < 8; ++ks) {
            const uint32_t ko = (uint32_t)ks * 32u;
            uint32_t a[2][4], b[4];
            LDSM4(a[0], a2T + ko);
            LDSM4(a[1], a2T + ko + 16u * AST);
            LDSM4(b, b2T + ko);
            #pragma unroll
            for (int fm = 0; fm < 2; ++fm)
                #pragma unroll
                for (int fn = 0; fn < 2; ++fn)
                    MMAF16(acc2[fm][fn], a[fm], b[fn], b[fn + 2]);
        }
    }

    // ---- epilogue 2: relu(+b2), dot w3, quad-reduce, cross-band add ----
    #pragma unroll
    for (int fm = 0; fm < 2; ++fm)
        #pragma unroll
        for (int rh = 0; rh < 2; ++rh) {
            float s = 0.f;
            #pragma unroll
            for (int fn = 0; fn < 2; ++fn) {
                const int col = wn2 * 16 + fn * 8 + (lid & 3) * 2;
                float h0 = fmaxf(acc2[fm][fn][rh * 2 + 0] + s_b2[col],     0.f);
                float h1 = fmaxf(acc2[fm][fn][rh * 2 + 1] + s_b2[col + 1], 0.f);
                s = fmaf(h0, s_w3[col], fmaf(h1, s_w3[col + 1], s));
            }
            s += __shfl_xor_sync(0xffffffffu, s, 1);
            s += __shfl_xor_sync(0xffffffffu, s, 2);
            if ((lid & 3) == 0)
                s_part[wm2 * 32 + fm * 16 + rh * 8 + (lid >> 2)][wn2] = s;
        }
    __syncthreads();
    if (tid < TILE_E) {
        int e = e0 + tid;
        if (e < E)
            out[e] = s_part[tid][0] + s_part[tid][1]
                   + s_part[tid][2] + s_part[tid][3] + s_b3;
    }
}

extern "C" void kernel_launch(void* const* d_in, const int* in_sizes, int n_in,
                              void* d_out, int out_size) {
    const float* z  = (const float*)d_in[0];
    const void*  ei = d_in[1];
    const float* W1 = (const float*)d_in[2];
    const float* b1 = (const float*)d_in[3];
    const float* W2 = (const float*)d_in[4];
    const float* b2 = (const float*)d_in[5];
    const float* W3 = (const float*)d_in[6];
    const float* b3 = (const float*)d_in[7];
    float* out = (float*)d_out;

    const int E      = out_size;
    const int nNodes = in_sizes[0] / HDIM;

    prep_kernel<<<256, 256>>>(W1, W2);

    cudaFuncSetAttribute(link_mma_kernel,
                         cudaFuncAttributeMaxDynamicSharedMemorySize, SMEM_DYN);
    const int grid = (E + TILE_E - 1) / TILE_E;
    link_mma_kernel<<<grid, NTHREADS, SMEM_DYN>>>(z, ei, b1, b2, W3, b3,
                                                  out, E, nNodes);
}

// round 12
// speedup vs baseline: 3.5485x; 1.0244x over previous
#include <cuda_runtime.h>
#include <cuda_fp16.h>
#include <cstdint>
#include <math.h>

#define TILE_E   128
#define NTHREADS 512
#define HDIM     128
#define AST      272u  // bytes/row for all fp16 tiles (68 words -> conflict-free ldsm)

// ---------------- global scratch: transposed fp16 weights ----------------
__device__ __half g_W1T[128 * 512];   // [n][k] from W1[k][n]
__device__ __half g_W2T[64 * 128];    // [n][k] from W2[k][n]

__global__ void prep_kernel(const float* __restrict__ W1, const float* __restrict__ W2) {
    int i = blockIdx.x * blockDim.x + threadIdx.x;
    if (i < 128 * 512) {
        int n = i >> 9, k = i & 511;
        g_W1T[i] = __float2half_rn(W1[k * 128 + n]);
    }
    if (i < 64 * 128) {
        int n = i >> 7, k = i & 127;
        g_W2T[i] = __float2half_rn(W2[k * 64 + n]);
    }
}

// ---------------- helpers ----------------
__device__ __forceinline__ uint32_t smem_u32(const void* p) {
    uint32_t a;
    asm("{ .reg .u64 t; cvta.to.shared.u64 t, %1; cvt.u32.u64 %0, t; }" : "=r"(a) : "l"(p));
    return a;
}
#define STS32(addr, v) \
    asm volatile("st.shared.b32 [%0], %1;" :: "r"(addr), "r"(v) : "memory")
#define STS64V(addr, v0, v1) \
    asm volatile("st.shared.v2.b32 [%0], {%1,%2};" :: "r"(addr), "r"(v0), "r"(v1) : "memory")
#define CP16(saddr, gaddr) \
    asm volatile("cp.async.cg.shared.global [%0], [%1], 16;" \
        :: "r"(saddr), "l"(gaddr) : "memory")
#define CP_COMMIT() asm volatile("cp.async.commit_group;" ::: "memory")
#define CP_WAIT0()  asm volatile("cp.async.wait_group 0;" ::: "memory")
#define LDSM4(r, a) \
    asm volatile("ldmatrix.sync.aligned.m8n8.x4.shared.b16 {%0,%1,%2,%3}, [%4];" \
        : "=r"((r)[0]), "=r"((r)[1]), "=r"((r)[2]), "=r"((r)[3]) : "r"(a))
#define MMAF16(c, a, b0v, b1v) \
    asm volatile("mma.sync.aligned.m16n8k16.row.col.f32.f16.f16.f32 " \
        "{%0,%1,%2,%3}, {%4,%5,%6,%7}, {%8,%9}, {%0,%1,%2,%3};" \
        : "+f"((c)[0]), "+f"((c)[1]), "+f"((c)[2]), "+f"((c)[3]) \
        : "r"((a)[0]), "r"((a)[1]), "r"((a)[2]), "r"((a)[3]), "r"(b0v), "r"(b1v))

__device__ __forceinline__ uint32_t packh2(float x0, float x1) {
    uint32_t r;
    asm("cvt.rn.f16x2.f32 %0, %1, %2;" : "=r"(r) : "f"(x1), "f"(x0));
    return r;
}

// dynamic smem layout: W1 segs (4 x 128x272) | W2 (64x272) | A0 | A1
#define W1S(i)  (sb + (uint32_t)(i) * 34816u)
#define W2_OFF  139264u
#define A0_OFF  156672u
#define A1_OFF  191488u
#define SMEM_DYN 226304

__global__ __launch_bounds__(NTHREADS, 1)
void link_mma_kernel(const float* __restrict__ z,
                     const void* __restrict__ ei_raw,
                     const float* __restrict__ b1g,
                     const float* __restrict__ b2g,
                     const float* __restrict__ w3g,
                     const float* __restrict__ b3g,
                     float* __restrict__ out,
                     int E, int nNodes)
{
    extern __shared__ char dynraw[];
    __shared__ int   s_src[TILE_E], s_dst[TILE_E];
    __shared__ float s_b1[128], s_b2[64], s_w3[64];
    __shared__ float s_b3;
    __shared__ int   s_is64;

    const int tid = threadIdx.x;
    const int wid = tid >> 5;
    const int lid = tid & 31;
    const uint32_t sb = smem_u32(dynraw);

    // ---- one-time setup ----
    if (tid == 0) {
        const long long* e64 = (const long long*)ei_raw;
        int ok = 1;
        #pragma unroll
        for (int i = 0; i < 8; ++i) {
            long long v = e64[i];
            if (v < 0 || v >= (long long)nNodes) { ok = 0; break; }
        }
        s_is64 = ok;
        s_b3 = b3g[0];
    }
    if (tid < 128)      s_b1[tid] = b1g[tid];
    else if (tid < 192) s_b2[tid - 128] = b2g[tid - 128];
    else if (tid < 256) s_w3[tid - 192] = w3g[tid - 192];

    // weights -> smem (once)
    {
        const char* srcW1 = (const char*)g_W1T;
        #pragma unroll
        for (int it = 0; it < 16; ++it) {
            int idx = tid + it * NTHREADS;     // 0..8191
            int seg = idx >> 11;
            int n   = (idx >> 4) & 127;
            int q   = idx & 15;
            uint32_t goff = (uint32_t)n * 1024u + (uint32_t)seg * 256u + (uint32_t)q * 16u;
            CP16(W1S(seg) + (uint32_t)n * AST + (uint32_t)q * 16u, srcW1 + goff);
        }
        const char* srcW2 = (const char*)g_W2T;
        #pragma unroll
        for (int it = 0; it < 2; ++it) {
            int idx = tid + it * NTHREADS;     // 0..1023
            int n = idx >> 4, q = idx & 15;
            CP16(sb + W2_OFF + (uint32_t)n * AST + (uint32_t)q * 16u,
                 srcW2 + (uint32_t)n * 256u + (uint32_t)q * 16u);
        }
        CP_COMMIT();
        CP_WAIT0();
    }
    __syncthreads();

    const int is64 = s_is64;
    const uint32_t lrow = (uint32_t)(lid & 15);
    const uint32_t lcol = (uint32_t)(lid >> 4) * 8;
    const bool is_producer = (wid >= 8);
    const int wb = wid & 7;

    const int wmC = wid >> 1;      // consumer GEMM1: 32 rows x 64 cols
    const int wnC = wid & 1;
    const int wm2 = wid >> 2;      // GEMM2: 32 rows x 16 cols
    const int wn2 = wid & 3;

    // ---- tile helpers ----
    auto fill_z = [&](const int* idxs, uint32_t dstA) {
        float4 v[16];
        #pragma unroll
        for (int i = 0; i < 16; ++i) {
            int m = wb * 16 + i;
            v[i] = *(const float4*)(z + (size_t)idxs[m] * HDIM + lid * 4);
        }
        #pragma unroll
        for (int i = 0; i < 16; ++i) {
            int m = wb * 16 + i;
            STS64V(dstA + (uint32_t)m * AST + (uint32_t)lid * 8,
                   packh2(v[i].x, v[i].y), packh2(v[i].z, v[i].w));
        }
    };
    auto fill_pd = [&](int op, uint32_t dstA) {   // 0: prod, 1: absdiff
        #pragma unroll
        for (int half = 0; half < 2; ++half) {
            float4 s4[8], d4[8];
            #pragma unroll
            for (int j = 0; j < 8; ++j) {
                int m = wb * 16 + half * 8 + j;
                s4[j] = *(const float4*)(z + (size_t)s_src[m] * HDIM + lid * 4);
                d4[j] = *(const float4*)(z + (size_t)s_dst[m] * HDIM + lid * 4);
            }
            #pragma unroll
            for (int j = 0; j < 8; ++j) {
                int m = wb * 16 + half * 8 + j;
                float4 r;
                if (op == 0) {
                    r.x = s4[j].x * d4[j].x; r.y = s4[j].y * d4[j].y;
                    r.z = s4[j].z * d4[j].z; r.w = s4[j].w * d4[j].w;
                } else {
                    r.x = fabsf(s4[j].x - d4[j].x); r.y = fabsf(s4[j].y - d4[j].y);
                    r.z = fabsf(s4[j].z - d4[j].z); r.w = fabsf(s4[j].w - d4[j].w);
                }
                STS64V(dstA + (uint32_t)m * AST + (uint32_t)lid * 8,
                       packh2(r.x, r.y), packh2(r.z, r.w));
            }
        }
    };

    const int nTiles = (E + TILE_E - 1) / TILE_E;

    for (int t = blockIdx.x; t < nTiles; t += gridDim.x) {
        const int e0 = t * TILE_E;

        __syncthreads();   // previous tile's reads of s_src/s_dst/A0/A1 complete
        if (tid < 256) {
            int tt = tid & (TILE_E - 1);
            int e = e0 + tt; if (e >= E) e = 0;
            int v;
            if (tid < TILE_E) {
                v = is64 ? (int)((const long long*)ei_raw)[e] : ((const int*)ei_raw)[e];
                s_src[tt] = min(max(v, 0), nNodes - 1);
            } else {
                v = is64 ? (int)((const long long*)ei_raw)[(size_t)E + e]
                         : ((const int*)ei_raw)[(size_t)E + e];
                s_dst[tt] = min(max(v, 0), nNodes - 1);
            }
        }
        __syncthreads();

        // fills: producers src->A0, consumers dst->A1 (parallel)
        if (is_producer) fill_z(s_src, sb + A0_OFF);
        else             fill_z(s_dst, sb + A1_OFF);
        __syncthreads();

        float acc[2][8][4];
        #pragma unroll
        for (int a = 0; a < 2; ++a)
            #pragma unroll
            for (int b = 0; b < 8; ++b)
                #pragma unroll
                for (int d = 0; d < 4; ++d) acc[a][b][d] = 0.f;

        // one k=128 GEMM1 phase
        auto consumer_mma = [&](uint32_t Abuf, uint32_t Bbuf) {
            const uint32_t aT = Abuf + (wmC * 32u + lrow) * AST + lcol * 2u;
            const uint32_t bT = Bbuf + (wnC * 64u + lrow) * AST + lcol * 2u;
            #pragma unroll
            for (int ks = 0; ks < 8; ++ks) {
                const uint32_t ko = (uint32_t)ks * 32u;
                uint32_t a[2][4];
                LDSM4(a[0], aT + ko);
                LDSM4(a[1], aT + ko + 16u * AST);
                #pragma unroll
                for (int gg = 0; gg < 2; ++gg) {
                    uint32_t b[2][4];
                    #pragma unroll
                    for (int gi = 0; gi < 2; ++gi) {
                        uint32_t rb = ko + (uint32_t)(gg * 2 + gi) * 16u * AST;
                        LDSM4(b[gi], bT + rb);
                    }
                    #pragma unroll
                    for (int fm = 0; fm < 2; ++fm)
                        #pragma unroll
                        for (int q = 0; q < 4; ++q) {
                            const int gi = q >> 1, sel = q & 1;
                            const int fn = gg * 4 + q;
                            MMAF16(acc[fm][fn], a[fm], b[gi][sel], b[gi][sel + 2]);
                        }
                }
            }
        };

        // phase 0: MMA(src A0, seg0)
        if (!is_producer) consumer_mma(sb + A0_OFF, W1S(0));
        __syncthreads();
        // phase 1: MMA(dst A1, seg1) | producers: prod -> A0
        if (is_producer) fill_pd(0, sb + A0_OFF);
        else             consumer_mma(sb + A1_OFF, W1S(1));
        __syncthreads();
        // phase 2: MMA(prod A0, seg2) | producers: diff -> A1
        if (is_producer) fill_pd(1, sb + A1_OFF);
        else             consumer_mma(sb + A0_OFF, W1S(2));
        __syncthreads();
        // phase 3: MMA(diff A1, seg3)
        if (!is_producer) consumer_mma(sb + A1_OFF, W1S(3));
        __syncthreads();

        // epilogue 1: consumers: relu(+b1) -> fp16 -> h1 tile in A0
        if (!is_producer) {
            const uint32_t a2 = sb + A0_OFF;
            #pragma unroll
            for (int fm = 0; fm < 2; ++fm)
                #pragma unroll
                for (int fn = 0; fn < 8; ++fn) {
                    const int col  = wnC * 64 + fn * 8 + (lid & 3) * 2;
                    const int row0 = wmC * 32 + fm * 16 + (lid >> 2);
                    float x0 = fmaxf(acc[fm][fn][0] + s_b1[col],     0.f);
                    float x1 = fmaxf(acc[fm][fn][1] + s_b1[col + 1], 0.f);
                    float x2 = fmaxf(acc[fm][fn][2] + s_b1[col],     0.f);
                    float x3 = fmaxf(acc[fm][fn][3] + s_b1[col + 1], 0.f);
                    uint32_t o0 = (uint32_t)row0 * AST + (uint32_t)col * 2;
                    STS32(a2 + o0, packh2(x0, x1));
                    STS32(a2 + o0 + 8u * AST, packh2(x2, x3));
                }
        }
        __syncthreads();

        // GEMM2 (all 16 warps): [128,128] x [64,128]^T, warp tile 32x16
        float acc2[2][2][4];
        #pragma unroll
        for (int a = 0; a < 2; ++a)
            #pragma unroll
            for (int b = 0; b < 2; ++b)
                #pragma unroll
                for (int d = 0; d < 4; ++d) acc2[a][b][d] = 0.f;
        {
            const uint32_t a2T = sb + A0_OFF + (wm2 * 32u + lrow) * AST + lcol * 2u;
            const uint32_t b2T = sb + W2_OFF + (wn2 * 16u + lrow) * AST + lcol * 2u;
            #pragma unroll
            for (int ks = 0; ks < 8; ++ks) {
                const uint32_t ko = (uint32_t)ks * 32u;
                uint32_t a[2][4], b[4];
                LDSM4(a[0], a2T + ko);
                LDSM4(a[1], a2T + ko + 16u * AST);
                LDSM4(b, b2T + ko);
                #pragma unroll
                for (int fm = 0; fm < 2; ++fm)
                    #pragma unroll
                    for (int fn = 0; fn < 2; ++fn)
                        MMAF16(acc2[fm][fn], a[fm], b[fn], b[fn + 2]);
            }
        }

        // epilogue 2: relu(+b2), dot w3, quad-reduce, partials in A1 overlay
        const uint32_t spart = sb + A1_OFF;
        #pragma unroll
        for (int fm = 0; fm < 2; ++fm)
            #pragma unroll
            for (int rh = 0; rh < 2; ++rh) {
                float s = 0.f;
                #pragma unroll
                for (int fn = 0; fn < 2; ++fn) {
                    const int col = wn2 * 16 + fn * 8 + (lid & 3) * 2;
                    float h0 = fmaxf(acc2[fm][fn][rh * 2 + 0] + s_b2[col],     0.f);
                    float h1 = fmaxf(acc2[fm][fn][rh * 2 + 1] + s_b2[col + 1], 0.f);
                    s = fmaf(h0, s_w3[col], fmaf(h1, s_w3[col + 1], s));
                }
                s += __shfl_xor_sync(0xffffffffu, s, 1);
                s += __shfl_xor_sync(0xffffffffu, s, 2);
                if ((lid & 3) == 0) {
                    int row = wm2 * 32 + fm * 16 + rh * 8 + (lid >> 2);
                    STS32(spart + (uint32_t)(row * 4 + wn2) * 4u, __float_as_uint(s));
                }
            }
        __syncthreads();
        if (tid < TILE_E) {
            const float* part = (const float*)(dynraw + A1_OFF);
            int e = e0 + tid;
            if (e < E)
                out[e] = part[tid * 4 + 0] + part[tid * 4 + 1]
                       + part[tid * 4 + 2] + part[tid * 4 + 3] + s_b3;
        }
    }
}

extern "C" void kernel_launch(void* const* d_in, const int* in_sizes, int n_in,
                              void* d_out, int out_size) {
    const float* z  = (const float*)d_in[0];
    const void*  ei = d_in[1];
    const float* W1 = (const float*)d_in[2];
    const float* b1 = (const float*)d_in[3];
    const float* W2 = (const float*)d_in[4];
    const float* b2 = (const float*)d_in[5];
    const float* W3 = (const float*)d_in[6];
    const float* b3 = (const float*)d_in[7];
    float* out = (float*)d_out;

    const int E      = out_size;
    const int nNodes = in_sizes[0] / HDIM;

    prep_kernel<<<256, 256>>>(W1, W2);

    cudaFuncSetAttribute(link_mma_kernel,
                         cudaFuncAttributeMaxDynamicSharedMemorySize, SMEM_DYN);

    int dev = 0, smCount = 148;
    cudaGetDevice(&dev);
    cudaDeviceGetAttribute(&smCount, cudaDevAttrMultiProcessorCount, dev);
    const int nTiles = (E + TILE_E - 1) / TILE_E;
    const int grid = smCount < nTiles ? smCount : nTiles;

    link_mma_kernel<<<grid, NTHREADS, SMEM_DYN>>>(z, ei, b1, b2, W3, b3,
                                                  out, E, nNodes);
}

// round 13
// speedup vs baseline: 3.7155x; 1.0471x over previous
#include <cuda_runtime.h>
#include <cuda_fp16.h>
#include <cstdint>
#include <math.h>

#define TILE_E   128
#define NTHREADS 512
#define HDIM     128
#define AST      272u  // bytes/row for fp16 tiles (68 words -> conflict-free ldsm)

// ---------------- global scratch: transposed fp16 weights ----------------
__device__ __half g_W1T[128 * 512];   // [n][k] from W1[k][n]
__device__ __half g_W2T[64 * 128];    // [n][k] from W2[k][n]

__global__ void prep_kernel(const float* __restrict__ W1, const float* __restrict__ W2) {
    int i = blockIdx.x * blockDim.x + threadIdx.x;
    if (i < 128 * 512) {
        int n = i >> 9, k = i & 511;
        g_W1T[i] = __float2half_rn(W1[k * 128 + n]);
    }
    if (i < 64 * 128) {
        int n = i >> 7, k = i & 127;
        g_W2T[i] = __float2half_rn(W2[k * 64 + n]);
    }
}

// ---------------- helpers ----------------
__device__ __forceinline__ uint32_t smem_u32(const void* p) {
    uint32_t a;
    asm("{ .reg .u64 t; cvta.to.shared.u64 t, %1; cvt.u32.u64 %0, t; }" : "=r"(a) : "l"(p));
    return a;
}
#define STS32(addr, v) \
    asm volatile("st.shared.b32 [%0], %1;" :: "r"(addr), "r"(v) : "memory")
#define STS64V(addr, v0, v1) \
    asm volatile("st.shared.v2.b32 [%0], {%1,%2};" :: "r"(addr), "r"(v0), "r"(v1) : "memory")
#define CP16(saddr, gaddr) \
    asm volatile("cp.async.cg.shared.global [%0], [%1], 16;" \
        :: "r"(saddr), "l"(gaddr) : "memory")
#define CP_COMMIT() asm volatile("cp.async.commit_group;" ::: "memory")
#define CP_WAIT0()  asm volatile("cp.async.wait_group 0;" ::: "memory")
#define LDSM4(r, a) \
    asm volatile("ldmatrix.sync.aligned.m8n8.x4.shared.b16 {%0,%1,%2,%3}, [%4];" \
        : "=r"((r)[0]), "=r"((r)[1]), "=r"((r)[2]), "=r"((r)[3]) : "r"(a))
#define MMAF16(c, a, b0v, b1v) \
    asm volatile("mma.sync.aligned.m16n8k16.row.col.f32.f16.f16.f32 " \
        "{%0,%1,%2,%3}, {%4,%5,%6,%7}, {%8,%9}, {%0,%1,%2,%3};" \
        : "+f"((c)[0]), "+f"((c)[1]), "+f"((c)[2]), "+f"((c)[3]) \
        : "r"((a)[0]), "r"((a)[1]), "r"((a)[2]), "r"((a)[3]), "r"(b0v), "r"(b1v))

__device__ __forceinline__ uint32_t packh2(float x0, float x1) {
    uint32_t r;
    asm("cvt.rn.f16x2.f32 %0, %1, %2;" : "=r"(r) : "f"(x1), "f"(x0));
    return r;
}

// dynamic smem: W1 segs (4 x 128x272) | W2 (64x272) | A region per group (2x)
#define W1S(i)  (sb + (uint32_t)(i) * 34816u)
#define W2_OFF  139264u
#define A_OFF   156672u
#define SMEM_DYN 226304

__global__ __launch_bounds__(NTHREADS, 1)
void link_mma_kernel(const float* __restrict__ z,
                     const void* __restrict__ ei_raw,
                     const float* __restrict__ b1g,
                     const float* __restrict__ b2g,
                     const float* __restrict__ w3g,
                     const float* __restrict__ b3g,
                     float* __restrict__ out,
                     int E, int nNodes)
{
    extern __shared__ char dynraw[];
    __shared__ int   s_src[2][TILE_E], s_dst[2][TILE_E];
    __shared__ float s_b1[128], s_b2[64], s_w3[64];
    __shared__ float s_b3;
    __shared__ int   s_is64;

    const int tid = threadIdx.x;
    const int wid = tid >> 5;
    const int lid = tid & 31;
    const uint32_t sb = smem_u32(dynraw);

    // ---- one-time setup ----
    if (tid == 0) {
        const long long* e64 = (const long long*)ei_raw;
        int ok = 1;
        #pragma unroll
        for (int i = 0; i < 8; ++i) {
            long long v = e64[i];
            if (v < 0 || v >= (long long)nNodes) { ok = 0; break; }
        }
        s_is64 = ok;
        s_b3 = b3g[0];
    }
    if (tid < 128)      s_b1[tid] = b1g[tid];
    else if (tid < 192) s_b2[tid - 128] = b2g[tid - 128];
    else if (tid < 256) s_w3[tid - 192] = w3g[tid - 192];

    // weights -> smem (once, whole CTA)
    {
        const char* srcW1 = (const char*)g_W1T;
        #pragma unroll
        for (int it = 0; it < 16; ++it) {
            int idx = tid + it * NTHREADS;     // 0..8191
            int seg = idx >> 11;
            int n   = (idx >> 4) & 127;
            int q   = idx & 15;
            uint32_t goff = (uint32_t)n * 1024u + (uint32_t)seg * 256u + (uint32_t)q * 16u;
            CP16(W1S(seg) + (uint32_t)n * AST + (uint32_t)q * 16u, srcW1 + goff);
        }
        const char* srcW2 = (const char*)g_W2T;
        #pragma unroll
        for (int it = 0; it < 2; ++it) {
            int idx = tid + it * NTHREADS;     // 0..1023
            int n = idx >> 4, q = idx & 15;
            CP16(sb + W2_OFF + (uint32_t)n * AST + (uint32_t)q * 16u,
                 srcW2 + (uint32_t)n * 256u + (uint32_t)q * 16u);
        }
        CP_COMMIT();
        CP_WAIT0();
    }
    __syncthreads();

    const int is64 = s_is64;
    const uint32_t lrow = (uint32_t)(lid & 15);
    const uint32_t lcol = (uint32_t)(lid >> 4) * 8;

    const int g     = wid >> 3;        // 0/1 : independent tile pipeline
    const int wg    = wid & 7;         // warp within group
    const int tid_g = tid & 255;       // thread within group
    const uint32_t Ag = sb + A_OFF + (uint32_t)g * 34816u;

    #define GBAR() asm volatile("bar.sync %0, 256;" :: "r"(g + 1) : "memory")

    // GEMM1 warp tile: 32 rows x 64 cols (wmG 0..3, wnG 0..1)
    const int wmG = wg >> 1;
    const int wnG = wg & 1;
    // GEMM2 warp tile: 32 rows x 32 cols (wm2 0..3, wn2 0..1)
    const int wm2 = wg >> 1;
    const int wn2 = wg & 1;

    // ---- group-scope helpers (8 warps, 16 rows/warp) ----
    auto fill_z = [&](const int* idxs, uint32_t dstA) {
        #pragma unroll
        for (int h = 0; h < 2; ++h) {
            float4 v[8];
            #pragma unroll
            for (int j = 0; j < 8; ++j) {
                int m = wg * 16 + h * 8 + j;
                v[j] = *(const float4*)(z + (size_t)idxs[m] * HDIM + lid * 4);
            }
            #pragma unroll
            for (int j = 0; j < 8; ++j) {
                int m = wg * 16 + h * 8 + j;
                STS64V(dstA + (uint32_t)m * AST + (uint32_t)lid * 8,
                       packh2(v[j].x, v[j].y), packh2(v[j].z, v[j].w));
            }
        }
    };
    auto fill_pd = [&](int op, uint32_t dstA) {   // 0: prod, 1: absdiff
        #pragma unroll
        for (int q4 = 0; q4 < 4; ++q4) {
            float4 s4[4], d4[4];
            #pragma unroll
            for (int j = 0; j < 4; ++j) {
                int m = wg * 16 + q4 * 4 + j;
                s4[j] = *(const float4*)(z + (size_t)s_src[g][m] * HDIM + lid * 4);
                d4[j] = *(const float4*)(z + (size_t)s_dst[g][m] * HDIM + lid * 4);
            }
            #pragma unroll
            for (int j = 0; j < 4; ++j) {
                int m = wg * 16 + q4 * 4 + j;
                float4 r;
                if (op == 0) {
                    r.x = s4[j].x * d4[j].x; r.y = s4[j].y * d4[j].y;
                    r.z = s4[j].z * d4[j].z; r.w = s4[j].w * d4[j].w;
                } else {
                    r.x = fabsf(s4[j].x - d4[j].x); r.y = fabsf(s4[j].y - d4[j].y);
                    r.z = fabsf(s4[j].z - d4[j].z); r.w = fabsf(s4[j].w - d4[j].w);
                }
                STS64V(dstA + (uint32_t)m * AST + (uint32_t)lid * 8,
                       packh2(r.x, r.y), packh2(r.z, r.w));
            }
        }
    };

    const int nTiles = (E + TILE_E - 1) / TILE_E;

    for (int t = blockIdx.x * 2 + g; t < nTiles; t += gridDim.x * 2) {
        const int e0 = t * TILE_E;

        GBAR();   // prev tile fully done (incl. partial reads from Ag)
        if (tid_g < 256) {
            int tt = tid_g & (TILE_E - 1);
            int e = e0 + tt; if (e >= E) e = 0;
            int v;
            if (tid_g < TILE_E) {
                v = is64 ? (int)((const long long*)ei_raw)[e] : ((const int*)ei_raw)[e];
                s_src[g][tt] = min(max(v, 0), nNodes - 1);
            } else {
                v = is64 ? (int)((const long long*)ei_raw)[(size_t)E + e]
                         : ((const int*)ei_raw)[(size_t)E + e];
                s_dst[g][tt] = min(max(v, 0), nNodes - 1);
            }
        }
        GBAR();

        float acc[2][8][4];
        #pragma unroll
        for (int a = 0; a < 2; ++a)
            #pragma unroll
            for (int b = 0; b < 8; ++b)
                #pragma unroll
                for (int d = 0; d < 4; ++d) acc[a][b][d] = 0.f;

        auto mma_seg = [&](uint32_t Bbuf) {
            const uint32_t aT = Ag + (wmG * 32u + lrow) * AST + lcol * 2u;
            const uint32_t bT = Bbuf + (wnG * 64u + lrow) * AST + lcol * 2u;
            #pragma unroll
            for (int ks = 0; ks < 8; ++ks) {
                const uint32_t ko = (uint32_t)ks * 32u;
                uint32_t a[2][4];
                LDSM4(a[0], aT + ko);
                LDSM4(a[1], aT + ko + 16u * AST);
                #pragma unroll
                for (int gg = 0; gg < 2; ++gg) {
                    uint32_t b[2][4];
                    #pragma unroll
                    for (int gi = 0; gi < 2; ++gi) {
                        uint32_t rb = ko + (uint32_t)(gg * 2 + gi) * 16u * AST;
                        LDSM4(b[gi], bT + rb);
                    }
                    #pragma unroll
                    for (int fm = 0; fm < 2; ++fm)
                        #pragma unroll
                        for (int q = 0; q < 4; ++q) {
                            const int gi = q >> 1, sel = q & 1;
                            const int fn = gg * 4 + q;
                            MMAF16(acc[fm][fn], a[fm], b[gi][sel], b[gi][sel + 2]);
                        }
                }
            }
        };

        // seg0: src     seg1: dst     seg2: prod     seg3: absdiff
        fill_z(s_src[g], Ag); GBAR(); mma_seg(W1S(0)); GBAR();
        fill_z(s_dst[g], Ag); GBAR(); mma_seg(W1S(1)); GBAR();
        fill_pd(0, Ag);       GBAR(); mma_seg(W1S(2)); GBAR();
        fill_pd(1, Ag);       GBAR(); mma_seg(W1S(3)); GBAR();

        // epilogue 1: relu(+b1) -> fp16 -> h1 tile in Ag
        #pragma unroll
        for (int fm = 0; fm < 2; ++fm)
            #pragma unroll
            for (int fn = 0; fn < 8; ++fn) {
                const int col  = wnG * 64 + fn * 8 + (lid & 3) * 2;
                const int row0 = wmG * 32 + fm * 16 + (lid >> 2);
                float x0 = fmaxf(acc[fm][fn][0] + s_b1[col],     0.f);
                float x1 = fmaxf(acc[fm][fn][1] + s_b1[col + 1], 0.f);
                float x2 = fmaxf(acc[fm][fn][2] + s_b1[col],     0.f);
                float x3 = fmaxf(acc[fm][fn][3] + s_b1[col + 1], 0.f);
                uint32_t o0 = (uint32_t)row0 * AST + (uint32_t)col * 2;
                STS32(Ag + o0, packh2(x0, x1));
                STS32(Ag + o0 + 8u * AST, packh2(x2, x3));
            }
        GBAR();

        // GEMM2: [128,128] x [64,128]^T, warp tile 32 rows x 32 cols
        float acc2[2][4][4];
        #pragma unroll
        for (int a = 0; a < 2; ++a)
            #pragma unroll
            for (int b = 0; b < 4; ++b)
                #pragma unroll
                for (int d = 0; d < 4; ++d) acc2[a][b][d] = 0.f;
        {
            const uint32_t a2T = Ag + (wm2 * 32u + lrow) * AST + lcol * 2u;
            const uint32_t b2T = sb + W2_OFF + (wn2 * 32u + lrow) * AST + lcol * 2u;
            #pragma unroll
            for (int ks = 0; ks < 8; ++ks) {
                const uint32_t ko = (uint32_t)ks * 32u;
                uint32_t a[2][4], b[2][4];
                LDSM4(a[0], a2T + ko);
                LDSM4(a[1], a2T + ko + 16u * AST);
                LDSM4(b[0], b2T + ko);
                LDSM4(b[1], b2T + ko + 16u * AST);
                #pragma unroll
                for (int fm = 0; fm < 2; ++fm)
                    #pragma unroll
                    for (int fn = 0; fn < 4; ++fn) {
                        const int gi = fn >> 1, sel = fn & 1;
                        MMAF16(acc2[fm][fn], a[fm], b[gi][sel], b[gi][sel + 2]);
                    }
            }
        }
        GBAR();   // all GEMM2 reads of Ag done before partials overwrite it

        // epilogue 2: relu(+b2), dot w3, quad-reduce, partials -> Ag
        #pragma unroll
        for (int fm = 0; fm < 2; ++fm)
            #pragma unroll
            for (int rh = 0; rh < 2; ++rh) {
                float s = 0.f;
                #pragma unroll
                for (int fn = 0; fn < 4; ++fn) {
                    const int col = wn2 * 32 + fn * 8 + (lid & 3) * 2;
                    float h0 = fmaxf(acc2[fm][fn][rh * 2 + 0] + s_b2[col],     0.f);
                    float h1 = fmaxf(acc2[fm][fn][rh * 2 + 1] + s_b2[col + 1], 0.f);
                    s = fmaf(h0, s_w3[col], fmaf(h1, s_w3[col + 1], s));
                }
                s += __shfl_xor_sync(0xffffffffu, s, 1);
                s += __shfl_xor_sync(0xffffffffu, s, 2);
                if ((lid & 3) == 0) {
                    int row = wm2 * 32 + fm * 16 + rh * 8 + (lid >> 2);
                    STS32(Ag + (uint32_t)(row * 2 + wn2) * 4u, __float_as_uint(s));
                }
            }
        GBAR();
        if (tid_g < TILE_E) {
            const float* part = (const float*)(dynraw + A_OFF + g * 34816);
            int e = e0 + tid_g;
            if (e < E)
                out[e] = part[tid_g * 2 + 0] + part[tid_g * 2 + 1] + s_b3;
        }
    }
    #undef GBAR
}

extern "C" void kernel_launch(void* const* d_in, const int* in_sizes, int n_in,
                              void* d_out, int out_size) {
    const float* z  = (const float*)d_in[0];
    const void*  ei = d_in[1];
    const float* W1 = (const float*)d_in[2];
    const float* b1 = (const float*)d_in[3];
    const float* W2 = (const float*)d_in[4];
    const float* b2 = (const float*)d_in[5];
    const float* W3 = (const float*)d_in[6];
    const float* b3 = (const float*)d_in[7];
    float* out = (float*)d_out;

    const int E      = out_size;
    const int nNodes = in_sizes[0] / HDIM;

    prep_kernel<<<256, 256>>>(W1, W2);

    cudaFuncSetAttribute(link_mma_kernel,
                         cudaFuncAttributeMaxDynamicSharedMemorySize, SMEM_DYN);

    int dev = 0, smCount = 148;
    cudaGetDevice(&dev);
    cudaDeviceGetAttribute(&smCount, cudaDevAttrMultiProcessorCount, dev);
    const int nTiles = (E + TILE_E - 1) / TILE_E;
    int grid = (nTiles + 1) / 2;
    if (grid > smCount) grid = smCount;

    link_mma_kernel<<<grid, NTHREADS, SMEM_DYN>>>(z, ei, b1, b2, W3, b3,
                                                  out, E, nNodes);
}

// round 14
// speedup vs baseline: 4.0338x; 1.0857x over previous
#include <cuda_runtime.h>
#include <cuda_fp16.h>
#include <cstdint>
#include <math.h>

#define TILE_E   128
#define NTHREADS 512
#define HDIM     128
#define ASTH     144u  // half-tile row stride (36 words -> conflict-free ldsm)
#define WST      272u  // weight-tile row stride (68 words -> conflict-free ldsm)

// ---------------- global scratch: transposed fp16 weights ----------------
__device__ __half g_W1T[128 * 512];   // [n][k] from W1[k][n]
__device__ __half g_W2T[64 * 128];    // [n][k] from W2[k][n]

__global__ void prep_kernel(const float* __restrict__ W1, const float* __restrict__ W2) {
    int i = blockIdx.x * blockDim.x + threadIdx.x;
    if (i < 128 * 512) {
        int n = i >> 9, k = i & 511;
        g_W1T[i] = __float2half_rn(W1[k * 128 + n]);
    }
    if (i < 64 * 128) {
        int n = i >> 7, k = i & 127;
        g_W2T[i] = __float2half_rn(W2[k * 64 + n]);
    }
}

// ---------------- helpers ----------------
__device__ __forceinline__ uint32_t smem_u32(const void* p) {
    uint32_t a;
    asm("{ .reg .u64 t; cvta.to.shared.u64 t, %1; cvt.u32.u64 %0, t; }" : "=r"(a) : "l"(p));
    return a;
}
#define STS32(addr, v) \
    asm volatile("st.shared.b32 [%0], %1;" :: "r"(addr), "r"(v) : "memory")
#define LDS32(v, addr) \
    asm volatile("ld.shared.b32 %0, [%1];" : "=r"(v) : "r"(addr))
#define CP16(saddr, gaddr) \
    asm volatile("cp.async.cg.shared.global [%0], [%1], 16;" \
        :: "r"(saddr), "l"(gaddr) : "memory")
#define CP_COMMIT() asm volatile("cp.async.commit_group;" ::: "memory")
#define CP_WAIT0()  asm volatile("cp.async.wait_group 0;" ::: "memory")
#define LDSM4(r, a) \
    asm volatile("ldmatrix.sync.aligned.m8n8.x4.shared.b16 {%0,%1,%2,%3}, [%4];" \
        : "=r"((r)[0]), "=r"((r)[1]), "=r"((r)[2]), "=r"((r)[3]) : "r"(a))
#define MMAF16(c, a, b0v, b1v) \
    asm volatile("mma.sync.aligned.m16n8k16.row.col.f32.f16.f16.f32 " \
        "{%0,%1,%2,%3}, {%4,%5,%6,%7}, {%8,%9}, {%0,%1,%2,%3};" \
        : "+f"((c)[0]), "+f"((c)[1]), "+f"((c)[2]), "+f"((c)[3]) \
        : "r"((a)[0]), "r"((a)[1]), "r"((a)[2]), "r"((a)[3]), "r"(b0v), "r"(b1v))

__device__ __forceinline__ uint32_t packh2(float x0, float x1) {
    uint32_t r;
    asm("cvt.rn.f16x2.f32 %0, %1, %2;" : "=r"(r) : "f"(x1), "f"(x0));
    return r;
}

// dynamic smem: W1 segs (4 x 128x272) | W2 (64x272) | per-group S,D half-tiles
#define W1S(i)  (sb + (uint32_t)(i) * 34816u)
#define W2_OFF  139264u
#define AG_OFF  156672u          // + g*36864 ; S at +0, D at +18432
#define SMEM_DYN 230400

__global__ __launch_bounds__(NTHREADS, 1)
void link_mma_kernel(const float* __restrict__ z,
                     const void* __restrict__ ei_raw,
                     const float* __restrict__ b1g,
                     const float* __restrict__ b2g,
                     const float* __restrict__ w3g,
                     const float* __restrict__ b3g,
                     float* __restrict__ out,
                     int E, int nNodes)
{
    extern __shared__ char dynraw[];
    __shared__ int s_is64;

    const int tid = threadIdx.x;
    const int wid = tid >> 5;
    const int lid = tid & 31;
    const uint32_t sb = smem_u32(dynraw);

    if (tid == 0) {
        const long long* e64 = (const long long*)ei_raw;
        int ok = 1;
        #pragma unroll
        for (int i = 0; i < 8; ++i) {
            long long v = e64[i];
            if (v < 0 || v >= (long long)nNodes) { ok = 0; break; }
        }
        s_is64 = ok;
    }

    // weights -> smem (once, whole CTA)
    {
        const char* srcW1 = (const char*)g_W1T;
        #pragma unroll
        for (int it = 0; it < 16; ++it) {
            int idx = tid + it * NTHREADS;     // 0..8191
            int seg = idx >> 11;
            int n   = (idx >> 4) & 127;
            int q   = idx & 15;
            uint32_t goff = (uint32_t)n * 1024u + (uint32_t)seg * 256u + (uint32_t)q * 16u;
            CP16(W1S(seg) + (uint32_t)n * WST + (uint32_t)q * 16u, srcW1 + goff);
        }
        const char* srcW2 = (const char*)g_W2T;
        #pragma unroll
        for (int it = 0; it < 2; ++it) {
            int idx = tid + it * NTHREADS;     // 0..1023
            int n = idx >> 4, q = idx & 15;
            CP16(sb + W2_OFF + (uint32_t)n * WST + (uint32_t)q * 16u,
                 srcW2 + (uint32_t)n * 256u + (uint32_t)q * 16u);
        }
        CP_COMMIT();
        CP_WAIT0();
    }
    __syncthreads();

    const int is64 = s_is64;
    const uint32_t lrow = (uint32_t)(lid & 15);
    const uint32_t lcol = (uint32_t)(lid >> 4) * 8;

    const int g     = wid >> 3;        // 0/1 : independent tile pipeline
    const int wg    = wid & 7;
    const int tid_g = tid & 255;
    const uint32_t Sb = sb + AG_OFF + (uint32_t)g * 36864u;
    const uint32_t Db = Sb + 18432u;

    #define GBAR() asm volatile("bar.sync %0, 256;" :: "r"(g + 1) : "memory")

    const int wmG = wg >> 1;           // GEMM1: 32 rows x 64 cols
    const int wnG = wg & 1;
    const int wm2 = wg >> 1;           // GEMM2: 32 rows x 32 cols
    const int wn2 = wg & 1;

    const int nTiles = (E + TILE_E - 1) / TILE_E;

    for (int t = blockIdx.x * 2 + g; t < nTiles; t += gridDim.x * 2) {
        const int e0 = t * TILE_E;

        GBAR();   // prev tile fully done (incl. partial reads from S)

        // per-warp edge indices in registers: lanes 0-15 src, 16-31 dst
        int myidx;
        {
            int e = e0 + wg * 16 + (lid & 15);
            if (e >= E) e = 0;
            if (lid < 16)
                myidx = is64 ? (int)((const long long*)ei_raw)[e] : ((const int*)ei_raw)[e];
            else
                myidx = is64 ? (int)((const long long*)ei_raw)[(size_t)E + e]
                             : ((const int*)ei_raw)[(size_t)E + e];
            myidx = min(max(myidx, 0), nNodes - 1);
        }

        float acc[2][8][4];
        #pragma unroll
        for (int a = 0; a < 2; ++a)
            #pragma unroll
            for (int b = 0; b < 8; ++b)
                #pragma unroll
                for (int d = 0; d < 4; ++d) acc[a][b][d] = 0.f;

        auto mma_half = [&](uint32_t Abuf, int seg, int h) {
            const uint32_t aT = Abuf + (wmG * 32u + lrow) * ASTH + lcol * 2u;
            const uint32_t bT = W1S(seg) + (wnG * 64u + lrow) * WST
                              + (uint32_t)h * 128u + lcol * 2u;
            #pragma unroll
            for (int ks = 0; ks < 4; ++ks) {
                const uint32_t ko = (uint32_t)ks * 32u;
                uint32_t a[2][4];
                LDSM4(a[0], aT + ko);
                LDSM4(a[1], aT + ko + 16u * ASTH);
                #pragma unroll
                for (int gg = 0; gg < 2; ++gg) {
                    uint32_t b[2][4];
                    #pragma unroll
                    for (int gi = 0; gi < 2; ++gi) {
                        uint32_t rb = ko + (uint32_t)(gg * 2 + gi) * 16u * WST;
                        LDSM4(b[gi], bT + rb);
                    }
                    #pragma unroll
                    for (int fm = 0; fm < 2; ++fm)
                        #pragma unroll
                        for (int q = 0; q < 4; ++q) {
                            const int gi = q >> 1, sel = q & 1;
                            const int fn = gg * 4 + q;
                            MMAF16(acc[fm][fn], a[fm], b[gi][sel], b[gi][sel + 2]);
                        }
                }
            }
        };

        #pragma unroll
        for (int h = 0; h < 2; ++h) {
            // ---- fill S (src half) and D (dst half) from global ----
            #pragma unroll
            for (int i = 0; i < 16; ++i) {
                int si = __shfl_sync(0xffffffffu, myidx, i);
                int di = __shfl_sync(0xffffffffu, myidx, 16 + i);
                float2 vsv = *(const float2*)(z + (size_t)si * HDIM + h * 64 + 2 * lid);
                float2 vdv = *(const float2*)(z + (size_t)di * HDIM + h * 64 + 2 * lid);
                uint32_t off = (uint32_t)(wg * 16 + i) * ASTH + (uint32_t)lid * 4u;
                STS32(Sb + off, packh2(vsv.x, vsv.y));
                STS32(Db + off, packh2(vdv.x, vdv.y));
            }
            GBAR();
            mma_half(Sb, 0, h);
            mma_half(Db, 1, h);
            GBAR();
            // ---- in-place: S -> prod, D -> |diff| (from fp16 tiles) ----
            #pragma unroll
            for (int i = 0; i < 16; ++i) {
                uint32_t off = (uint32_t)(wg * 16 + i) * ASTH + (uint32_t)lid * 4u;
                uint32_t su, du;
                LDS32(su, Sb + off);
                LDS32(du, Db + off);
                float2 sf = __half22float2(*reinterpret_cast<__half2*>(&su));
                float2 df = __half22float2(*reinterpret_cast<__half2*>(&du));
                STS32(Sb + off, packh2(sf.x * df.x, sf.y * df.y));
                STS32(Db + off, packh2(fabsf(sf.x - df.x), fabsf(sf.y - df.y)));
            }
            GBAR();
            mma_half(Sb, 2, h);
            mma_half(Db, 3, h);
            GBAR();
        }

        // ---- epilogue 1: relu(+b1) -> fp16 -> h1 halves (cols<64 -> S, else D) ----
        {
            const uint32_t reg = (wnG == 0) ? Sb : Db;
            #pragma unroll
            for (int fm = 0; fm < 2; ++fm)
                #pragma unroll
                for (int fn = 0; fn < 8; ++fn) {
                    const int lc   = fn * 8 + (lid & 3) * 2;        // local col 0..63
                    const int col  = wnG * 64 + lc;                 // global col
                    const int row0 = wmG * 32 + fm * 16 + (lid >> 2);
                    const float bb0 = __ldg(&b1g[col]);
                    const float bb1 = __ldg(&b1g[col + 1]);
                    float x0 = fmaxf(acc[fm][fn][0] + bb0, 0.f);
                    float x1 = fmaxf(acc[fm][fn][1] + bb1, 0.f);
                    float x2 = fmaxf(acc[fm][fn][2] + bb0, 0.f);
                    float x3 = fmaxf(acc[fm][fn][3] + bb1, 0.f);
                    uint32_t o0 = (uint32_t)row0 * ASTH + (uint32_t)lc * 2u;
                    STS32(reg + o0, packh2(x0, x1));
                    STS32(reg + o0 + 8u * ASTH, packh2(x2, x3));
                }
        }
        GBAR();

        // ---- GEMM2: h1 [128,128] x W2^T [64,128], warp tile 32x32, k halves ----
        float acc2[2][4][4];
        #pragma unroll
        for (int a = 0; a < 2; ++a)
            #pragma unroll
            for (int b = 0; b < 4; ++b)
                #pragma unroll
                for (int d = 0; d < 4; ++d) acc2[a][b][d] = 0.f;
        #pragma unroll
        for (int h = 0; h < 2; ++h) {
            const uint32_t a2T = (h ? Db : Sb) + (wm2 * 32u + lrow) * ASTH + lcol * 2u;
            const uint32_t b2T = sb + W2_OFF + (wn2 * 32u + lrow) * WST
                               + (uint32_t)h * 128u + lcol * 2u;
            #pragma unroll
            for (int ks = 0; ks < 4; ++ks) {
                const uint32_t ko = (uint32_t)ks * 32u;
                uint32_t a[2][4], b[2][4];
                LDSM4(a[0], a2T + ko);
                LDSM4(a[1], a2T + ko + 16u * ASTH);
                LDSM4(b[0], b2T + ko);
                LDSM4(b[1], b2T + ko + 16u * WST);
                #pragma unroll
                for (int fm = 0; fm < 2; ++fm)
                    #pragma unroll
                    for (int fn = 0; fn < 4; ++fn) {
                        const int gi = fn >> 1, sel = fn & 1;
                        MMAF16(acc2[fm][fn], a[fm], b[gi][sel], b[gi][sel + 2]);
                    }
            }
        }
        GBAR();   // all GEMM2 reads of S/D done before partials overwrite

        // ---- epilogue 2: relu(+b2), dot w3, quad-reduce, partials -> S ----
        #pragma unroll
        for (int fm = 0; fm < 2; ++fm)
            #pragma unroll
            for (int rh = 0; rh < 2; ++rh) {
                float s = 0.f;
                #pragma unroll
                for (int fn = 0; fn < 4; ++fn) {
                    const int col = wn2 * 32 + fn * 8 + (lid & 3) * 2;
                    float h0 = fmaxf(acc2[fm][fn][rh * 2 + 0] + __ldg(&b2g[col]),     0.f);
                    float h1 = fmaxf(acc2[fm][fn][rh * 2 + 1] + __ldg(&b2g[col + 1]), 0.f);
                    s = fmaf(h0, __ldg(&w3g[col]), fmaf(h1, __ldg(&w3g[col + 1]), s));
                }
                s += __shfl_xor_sync(0xffffffffu, s, 1);
                s += __shfl_xor_sync(0xffffffffu, s, 2);
                if ((lid & 3) == 0) {
                    int row = wm2 * 32 + fm * 16 + rh * 8 + (lid >> 2);
                    STS32(Sb + (uint32_t)(row * 2 + wn2) * 4u, __float_as_uint(s));
                }
            }
        GBAR();
        if (tid_g < TILE_E) {
            const float* part = (const float*)(dynraw + AG_OFF + g * 36864);
            int e = e0 + tid_g;
            if (e < E)
                out[e] = part[tid_g * 2 + 0] + part[tid_g * 2 + 1] + __ldg(&b3g[0]);
        }
    }
    #undef GBAR
}

extern "C" void kernel_launch(void* const* d_in, const int* in_sizes, int n_in,
                              void* d_out, int out_size) {
    const float* z  = (const float*)d_in[0];
    const void*  ei = d_in[1];
    const float* W1 = (const float*)d_in[2];
    const float* b1 = (const float*)d_in[3];
    const float* W2 = (const float*)d_in[4];
    const float* b2 = (const float*)d_in[5];
    const float* W3 = (const float*)d_in[6];
    const float* b3 = (const float*)d_in[7];
    float* out = (float*)d_out;

    const int E      = out_size;
    const int nNodes = in_sizes[0] / HDIM;

    prep_kernel<<<256, 256>>>(W1, W2);

    cudaFuncSetAttribute(link_mma_kernel,
                         cudaFuncAttributeMaxDynamicSharedMemorySize, SMEM_DYN);

    int dev = 0, smCount = 148;
    cudaGetDevice(&dev);
    cudaDeviceGetAttribute(&smCount, cudaDevAttrMultiProcessorCount, dev);
    const int nTiles = (E + TILE_E - 1) / TILE_E;
    int grid = (nTiles + 1) / 2;
    if (grid > smCount) grid = smCount;

    link_mma_kernel<<<grid, NTHREADS, SMEM_DYN>>>(z, ei, b1, b2, W3, b3,
                                                  out, E, nNodes);
}